// round 2
// baseline (speedup 1.0000x reference)
#include <cuda_runtime.h>
#include <math.h>

#define BB 8
#define NN_SEQ 1024
#define DD 1024
#define HH 16
#define DH 64
#define TT (BB * NN_SEQ)      // 8192 tokens
#define EE 4
#define MH 2048
#define LN_EPS 1e-5f

// ---------------- scratch (device globals; no allocations allowed) ----------
__device__ float g_Tr[BB * NN_SEQ * DD];
__device__ float g_S [BB * NN_SEQ * DD];
__device__ float g_Sn[BB * NN_SEQ * DD];
__device__ float g_q [BB * NN_SEQ * DD];
__device__ float g_k [BB * NN_SEQ * DD];
__device__ float g_v [BB * NN_SEQ * DD];
__device__ float g_y [BB * NN_SEQ * DD];
__device__ float g_xs[BB * NN_SEQ * DD];
__device__ float g_xf[BB * NN_SEQ * DD];
__device__ float g_h [TT * MH];
__device__ float g_gates[TT * EE];
__device__ float g_wts  [TT * EE];
__device__ float g_auxval[1];

// ---------------- kernel 1: decomposition + seasonal + LN1 ------------------
// one block per (b,n) row; 256 threads; each thread owns 4 channels.
__global__ __launch_bounds__(256) void decomp_ln1_kernel(
    const float* __restrict__ x, const float* __restrict__ alpha,
    const float* __restrict__ dw7, const float* __restrict__ dw25,
    const float* __restrict__ dw49,
    const float* __restrict__ n1g, const float* __restrict__ n1b)
{
    int bn = blockIdx.x;
    int b = bn / NN_SEQ, n = bn % NN_SEQ;
    int tid = threadIdx.x;

    // softmax over alpha[0..2]
    float a0 = alpha[0], a1 = alpha[1], a2 = alpha[2];
    float mx = fmaxf(a0, fmaxf(a1, a2));
    float e0 = __expf(a0 - mx), e1 = __expf(a1 - mx), e2 = __expf(a2 - mx);
    float inv = 1.0f / (e0 + e1 + e2);
    float w0 = e0 * inv, w1 = e1 * inv, w2 = e2 * inv;

    const float* xb = x + (size_t)b * NN_SEQ * DD;
    float s_local[4];
    float sum = 0.f, sumsq = 0.f;

#pragma unroll
    for (int i = 0; i < 4; i++) {
        int d = tid + i * 256;
        // load reflect-padded window [-24, +24]
        float win[49];
#pragma unroll
        for (int j = 0; j < 49; j++) {
            int idx = n + j - 24;
            idx = idx < 0 ? -idx : idx;
            idx = idx >= NN_SEQ ? (2 * NN_SEQ - 2 - idx) : idx;
            win[j] = xb[(size_t)idx * DD + d];
        }
        float t7 = 0.f, t25 = 0.f, t49 = 0.f;
#pragma unroll
        for (int j = 0; j < 7; j++)  t7  += dw7 [d * 7  + j] * win[21 + j];
#pragma unroll
        for (int j = 0; j < 25; j++) t25 += dw25[d * 25 + j] * win[12 + j];
#pragma unroll
        for (int j = 0; j < 49; j++) t49 += dw49[d * 49 + j] * win[j];
        float tr = w0 * t7 + w1 * t25 + w2 * t49;
        float sv = win[24] - tr;            // x[b,n,d] - trend
        g_Tr[(size_t)bn * DD + d] = tr;
        g_S [(size_t)bn * DD + d] = sv;
        s_local[i] = sv;
        sum += sv; sumsq += sv * sv;
    }

    __shared__ float sh1[256], sh2[256];
    sh1[tid] = sum; sh2[tid] = sumsq;
    __syncthreads();
    for (int o = 128; o > 0; o >>= 1) {
        if (tid < o) { sh1[tid] += sh1[tid + o]; sh2[tid] += sh2[tid + o]; }
        __syncthreads();
    }
    float mean = sh1[0] * (1.0f / DD);
    float var  = sh2[0] * (1.0f / DD) - mean * mean;
    float rstd = rsqrtf(var + LN_EPS);

#pragma unroll
    for (int i = 0; i < 4; i++) {
        int d = tid + i * 256;
        g_Sn[(size_t)bn * DD + d] = (s_local[i] - mean) * rstd * n1g[d] + n1b[d];
    }
}

// ---------------- generic LN kernel ----------------------------------------
__global__ __launch_bounds__(256) void ln_kernel(
    const float* __restrict__ in, const float* __restrict__ g,
    const float* __restrict__ bta, float* __restrict__ out)
{
    int bn = blockIdx.x;
    int tid = threadIdx.x;
    const float* row = in + (size_t)bn * DD;
    float v[4]; float sum = 0.f, sumsq = 0.f;
#pragma unroll
    for (int i = 0; i < 4; i++) {
        v[i] = row[tid + i * 256];
        sum += v[i]; sumsq += v[i] * v[i];
    }
    __shared__ float sh1[256], sh2[256];
    sh1[tid] = sum; sh2[tid] = sumsq;
    __syncthreads();
    for (int o = 128; o > 0; o >>= 1) {
        if (tid < o) { sh1[tid] += sh1[tid + o]; sh2[tid] += sh2[tid + o]; }
        __syncthreads();
    }
    float mean = sh1[0] * (1.0f / DD);
    float var  = sh2[0] * (1.0f / DD) - mean * mean;
    float rstd = rsqrtf(var + LN_EPS);
#pragma unroll
    for (int i = 0; i < 4; i++) {
        int d = tid + i * 256;
        out[(size_t)bn * DD + d] = (v[i] - mean) * rstd * g[d] + bta[d];
    }
}

// ---------------- tiled fp32 NT GEMM: C = A[MxK] * W[NxK]^T -----------------
// mode 0: C = acc + bias (+ addend)
// mode 1: C = gelu(acc + bias)
// mode 2: C += (acc + bias) * rowscale[row * rs_stride]
#define GTK 16
#define GSA 130   // smem stride: conflict-free for both store & fragment read
__global__ __launch_bounds__(256, 2) void gemm_nt(
    const float* __restrict__ A, const float* __restrict__ W,
    const float* __restrict__ bias, const float* __restrict__ addend,
    const float* __restrict__ rowscale, int rs_stride,
    float* __restrict__ C, int M, int Nn, int K, int mode)
{
    __shared__ float As[GTK][GSA];
    __shared__ float Ws[GTK][GSA];
    int tid = threadIdx.x;
    int tx = tid & 15, ty = tid >> 4;
    int m0 = blockIdx.y * 128, n0 = blockIdx.x * 128;

    float acc[8][8];
#pragma unroll
    for (int i = 0; i < 8; i++)
#pragma unroll
        for (int j = 0; j < 8; j++) acc[i][j] = 0.f;

    for (int k0 = 0; k0 < K; k0 += GTK) {
#pragma unroll
        for (int i = 0; i < 2; i++) {
            int lin = tid + i * 256;
            int row = lin >> 2, kc4 = lin & 3;
            float4 av = *(const float4*)&A[(size_t)(m0 + row) * K + k0 + kc4 * 4];
            As[kc4 * 4 + 0][row] = av.x; As[kc4 * 4 + 1][row] = av.y;
            As[kc4 * 4 + 2][row] = av.z; As[kc4 * 4 + 3][row] = av.w;
            float4 wv = *(const float4*)&W[(size_t)(n0 + row) * K + k0 + kc4 * 4];
            Ws[kc4 * 4 + 0][row] = wv.x; Ws[kc4 * 4 + 1][row] = wv.y;
            Ws[kc4 * 4 + 2][row] = wv.z; Ws[kc4 * 4 + 3][row] = wv.w;
        }
        __syncthreads();
#pragma unroll
        for (int kk = 0; kk < GTK; kk++) {
            float a[8], bb[8];
#pragma unroll
            for (int i = 0; i < 8; i++) {
                a[i]  = As[kk][ty + 16 * i];
                bb[i] = Ws[kk][tx + 16 * i];
            }
#pragma unroll
            for (int im = 0; im < 8; im++)
#pragma unroll
                for (int in = 0; in < 8; in++)
                    acc[im][in] += a[im] * bb[in];
        }
        __syncthreads();
    }

#pragma unroll
    for (int in = 0; in < 8; in++) {
        int col = n0 + tx + 16 * in;
        float bv = bias ? bias[col] : 0.f;
#pragma unroll
        for (int im = 0; im < 8; im++) {
            int row = m0 + ty + 16 * im;
            size_t off = (size_t)row * Nn + col;
            float val = acc[im][in] + bv;
            if (mode == 0) {
                if (addend) val += addend[off];
                C[off] = val;
            } else if (mode == 1) {
                C[off] = 0.5f * val * (1.0f + erff(val * 0.70710678118f));
            } else {
                C[off] += val * rowscale[(size_t)row * rs_stride];
            }
        }
    }
}

// ---------------- attention: warp-per-query streaming online softmax --------
__global__ __launch_bounds__(128) void attn_kernel(
    const float* __restrict__ q, const float* __restrict__ k,
    const float* __restrict__ v, float* __restrict__ y)
{
    int bh = blockIdx.x;
    int b = bh / HH, h = bh % HH;
    int qrow = blockIdx.y * 4 + (threadIdx.x >> 5);
    int lane = threadIdx.x & 31;

    size_t base = ((size_t)(b * NN_SEQ + qrow) * DD + h * DH);
    float2 qv = *(const float2*)&q[base + 2 * lane];
    float slope = exp2f(-0.5f * (float)(h + 1));

    const float* kb = k + (size_t)b * NN_SEQ * DD + h * DH + 2 * lane;
    const float* vb = v + (size_t)b * NN_SEQ * DD + h * DH + 2 * lane;

    float m = -1e30f, l = 0.f, a0 = 0.f, a1 = 0.f;
    for (int kk = 0; kk < NN_SEQ; kk++) {
        float2 kv = *(const float2*)&kb[(size_t)kk * DD];
        float s = qv.x * kv.x + qv.y * kv.y;
#pragma unroll
        for (int o = 16; o > 0; o >>= 1) s += __shfl_xor_sync(0xffffffffu, s, o);
        float dist = (kk > qrow) ? (float)(kk - qrow) : 0.f;
        s = s * 0.125f - slope * dist;
        float mn = fmaxf(m, s);
        float c = __expf(m - mn), p = __expf(s - mn);
        float2 vv = *(const float2*)&vb[(size_t)kk * DD];
        l  = l * c + p;
        a0 = a0 * c + p * vv.x;
        a1 = a1 * c + p * vv.y;
        m = mn;
    }
    float invl = 1.0f / l;
    y[base + 2 * lane]     = a0 * invl;
    y[base + 2 * lane + 1] = a1 * invl;
}

// ---------------- router: gates + top-2 weights -----------------------------
__global__ __launch_bounds__(128) void router_kernel(
    const float* __restrict__ xf, const float* __restrict__ rw)
{
    int t = blockIdx.x;
    int lane = threadIdx.x & 31, wrp = threadIdx.x >> 5;
    const float* xr = xf + (size_t)t * DD;
    const float* wr = rw + (size_t)wrp * DD;
    float s = 0.f;
    for (int i = lane; i < DD; i += 32) s += xr[i] * wr[i];
#pragma unroll
    for (int o = 16; o > 0; o >>= 1) s += __shfl_xor_sync(0xffffffffu, s, o);
    __shared__ float sh[4];
    if (lane == 0) sh[wrp] = s;
    __syncthreads();
    if (threadIdx.x == 0) {
        float g[4]; float mx = -1e30f;
#pragma unroll
        for (int e = 0; e < EE; e++) { g[e] = sh[e]; mx = fmaxf(mx, g[e]); }
        float sum = 0.f;
#pragma unroll
        for (int e = 0; e < EE; e++) { g[e] = __expf(g[e] - mx); sum += g[e]; }
        float inv = 1.0f / sum;
#pragma unroll
        for (int e = 0; e < EE; e++) { g[e] *= inv; g_gates[t * EE + e] = g[e]; }
        int i1 = 0;
#pragma unroll
        for (int e = 1; e < EE; e++) if (g[e] > g[i1]) i1 = e;
        int i2 = -1;
#pragma unroll
        for (int e = 0; e < EE; e++)
            if (e != i1 && (i2 < 0 || g[e] > g[i2])) i2 = e;
        float norm = fmaxf(g[i1] + g[i2], 1e-9f);
        float w4[4] = {0.f, 0.f, 0.f, 0.f};
        w4[i1] = g[i1] / norm;
        w4[i2] = g[i2] / norm;
#pragma unroll
        for (int e = 0; e < EE; e++) g_wts[t * EE + e] = w4[e];
    }
}

// ---------------- deterministic aux reduction -------------------------------
__global__ __launch_bounds__(256) void aux_reduce_kernel()
{
    int tid = threadIdx.x;
    float sg[EE] = {0.f, 0.f, 0.f, 0.f};
    float sc[EE] = {0.f, 0.f, 0.f, 0.f};
    for (int t = tid; t < TT; t += 256) {
#pragma unroll
        for (int e = 0; e < EE; e++) {
            sg[e] += g_gates[t * EE + e];
            sc[e] += (g_wts[t * EE + e] > 0.f) ? 1.f : 0.f;
        }
    }
    __shared__ float sh[256];
    float aux = 0.f;
#pragma unroll
    for (int e = 0; e < EE; e++) {
        sh[tid] = sg[e]; __syncthreads();
        for (int o = 128; o > 0; o >>= 1) {
            if (tid < o) sh[tid] += sh[tid + o];
            __syncthreads();
        }
        float tot_g = sh[0]; __syncthreads();
        sh[tid] = sc[e]; __syncthreads();
        for (int o = 128; o > 0; o >>= 1) {
            if (tid < o) sh[tid] += sh[tid + o];
            __syncthreads();
        }
        float tot_c = sh[0]; __syncthreads();
        aux += (tot_g / (float)TT) * (tot_c / (float)TT);
    }
    if (tid == 0) g_auxval[0] = (float)EE * aux;
}

// ---------------- final: + trend depthwise conv(k=5) + aux ------------------
__global__ __launch_bounds__(256) void final_kernel(
    const float* __restrict__ tw, const float* __restrict__ tb,
    float* __restrict__ out, int write_aux)
{
    int bn = blockIdx.x;
    int b = bn / NN_SEQ, n = bn % NN_SEQ;
    int tid = threadIdx.x;
#pragma unroll
    for (int i = 0; i < 4; i++) {
        int d = tid + i * 256;
        float vsum = g_xs[(size_t)bn * DD + d] + tb[d];
#pragma unroll
        for (int j = 0; j < 5; j++) {
            int nn = n - 2 + j;
            if (nn >= 0 && nn < NN_SEQ)
                vsum += tw[d * 5 + j] * g_Tr[((size_t)b * NN_SEQ + nn) * DD + d];
        }
        out[(size_t)bn * DD + d] = vsum;
    }
    if (bn == 0 && tid == 0 && write_aux)
        out[(size_t)BB * NN_SEQ * DD] = g_auxval[0];
}

// ---------------- host orchestration ---------------------------------------
extern "C" void kernel_launch(void* const* d_in, const int* in_sizes, int n_in,
                              void* d_out, int out_size)
{
    const float* x    = (const float*)d_in[0];
    const float* qw   = (const float*)d_in[1];
    const float* qb   = (const float*)d_in[2];
    const float* kw   = (const float*)d_in[3];
    const float* kb   = (const float*)d_in[4];
    const float* vw   = (const float*)d_in[5];
    const float* vb   = (const float*)d_in[6];
    const float* ow   = (const float*)d_in[7];
    const float* ob   = (const float*)d_in[8];
    const float* n1g  = (const float*)d_in[9];
    const float* n1b  = (const float*)d_in[10];
    const float* n2g  = (const float*)d_in[11];
    const float* n2b  = (const float*)d_in[12];
    const float* alpha= (const float*)d_in[13];
    const float* dw7  = (const float*)d_in[14];
    const float* dw25 = (const float*)d_in[15];
    const float* dw49 = (const float*)d_in[16];
    const float* rw   = (const float*)d_in[17];
    const float* ew1  = (const float*)d_in[18];
    const float* eb1  = (const float*)d_in[19];
    const float* ew2  = (const float*)d_in[20];
    const float* eb2  = (const float*)d_in[21];
    const float* tw   = (const float*)d_in[22];
    const float* tb   = (const float*)d_in[23];
    float* out = (float*)d_out;

    float *p_Sn, *p_q, *p_k, *p_v, *p_y, *p_xs, *p_xf, *p_h, *p_S, *p_wts;
    cudaGetSymbolAddress((void**)&p_Sn, g_Sn);
    cudaGetSymbolAddress((void**)&p_q,  g_q);
    cudaGetSymbolAddress((void**)&p_k,  g_k);
    cudaGetSymbolAddress((void**)&p_v,  g_v);
    cudaGetSymbolAddress((void**)&p_y,  g_y);
    cudaGetSymbolAddress((void**)&p_xs, g_xs);
    cudaGetSymbolAddress((void**)&p_xf, g_xf);
    cudaGetSymbolAddress((void**)&p_h,  g_h);
    cudaGetSymbolAddress((void**)&p_S,  g_S);
    cudaGetSymbolAddress((void**)&p_wts, g_wts);

    // 1) decomposition + seasonal + LN1
    decomp_ln1_kernel<<<BB * NN_SEQ, 256>>>(x, alpha, dw7, dw25, dw49, n1g, n1b);

    // 2) QKV projections: [T,1024] @ [1024,1024]^T
    dim3 gQ(DD / 128, TT / 128);
    gemm_nt<<<gQ, 256>>>(p_Sn, qw, qb, nullptr, nullptr, 0, p_q, TT, DD, DD, 0);
    gemm_nt<<<gQ, 256>>>(p_Sn, kw, kb, nullptr, nullptr, 0, p_k, TT, DD, DD, 0);
    gemm_nt<<<gQ, 256>>>(p_Sn, vw, vb, nullptr, nullptr, 0, p_v, TT, DD, DD, 0);

    // 3) ALiBi attention
    attn_kernel<<<dim3(BB * HH, NN_SEQ / 4), 128>>>(p_q, p_k, p_v, p_y);

    // 4) output projection fused with residual: x_s = S + (y @ ow^T + ob)
    gemm_nt<<<gQ, 256>>>(p_y, ow, ob, p_S, nullptr, 0, p_xs, TT, DD, DD, 0);

    // 5) LN2 -> xf
    ln_kernel<<<BB * NN_SEQ, 256>>>(p_xs, n2g, n2b, p_xf);

    // 6) router (gates + top-2 weights), deterministic aux
    router_kernel<<<TT, 128>>>(p_xf, rw);
    aux_reduce_kernel<<<1, 256>>>();

    // 7) MoE experts (dense): accumulate scaled outputs into x_s in place
    dim3 gE1(MH / 128, TT / 128);
    dim3 gE2(DD / 128, TT / 128);
    for (int e = 0; e < EE; e++) {
        gemm_nt<<<gE1, 256>>>(p_xf, ew1 + (size_t)e * MH * DD, eb1 + (size_t)e * MH,
                              nullptr, nullptr, 0, p_h, TT, MH, DD, 1);
        gemm_nt<<<gE2, 256>>>(p_h, ew2 + (size_t)e * DD * MH, eb2 + (size_t)e * DD,
                              nullptr, p_wts + e, EE, p_xs, TT, DD, MH, 2);
    }

    // 8) trend conv + final sum + aux scalar
    int write_aux = (out_size > BB * NN_SEQ * DD) ? 1 : 0;
    final_kernel<<<BB * NN_SEQ, 256>>>(tw, tb, out, write_aux);
}

// round 5
// speedup vs baseline: 1.1987x; 1.1987x over previous
#include <cuda_runtime.h>
#include <math.h>

#define BB 8
#define NN_SEQ 1024
#define DD 1024
#define HH 16
#define DH 64
#define TT (BB * NN_SEQ)      // 8192 tokens
#define EE 4
#define MH 2048
#define LN_EPS 1e-5f

// ---------------- scratch (device globals; no allocations allowed) ----------
__device__ float g_Tr[BB * NN_SEQ * DD];
__device__ float g_S [BB * NN_SEQ * DD];
__device__ float g_Sn[BB * NN_SEQ * DD];
__device__ float g_q [BB * NN_SEQ * DD];
__device__ float g_k [BB * NN_SEQ * DD];
__device__ float g_v [BB * NN_SEQ * DD];
__device__ float g_y [BB * NN_SEQ * DD];
__device__ float g_xs[BB * NN_SEQ * DD];
__device__ float g_xf[BB * NN_SEQ * DD];
__device__ float g_h [TT * MH];
__device__ float g_gates[TT * EE];
__device__ float g_wts  [TT * EE];
__device__ int   g_list [EE * TT];
__device__ float g_lw   [EE * TT];
__device__ int   g_cnt  [EE];
__device__ float g_auxval[1];

// ---------------- kernel 1: decomposition + seasonal + LN1 ------------------
__global__ __launch_bounds__(256) void decomp_ln1_kernel(
    const float* __restrict__ x, const float* __restrict__ alpha,
    const float* __restrict__ dw7, const float* __restrict__ dw25,
    const float* __restrict__ dw49,
    const float* __restrict__ n1g, const float* __restrict__ n1b)
{
    int bn = blockIdx.x;
    int b = bn / NN_SEQ, n = bn % NN_SEQ;
    int tid = threadIdx.x;

    float a0 = alpha[0], a1 = alpha[1], a2 = alpha[2];
    float mx = fmaxf(a0, fmaxf(a1, a2));
    float e0 = __expf(a0 - mx), e1 = __expf(a1 - mx), e2 = __expf(a2 - mx);
    float inv = 1.0f / (e0 + e1 + e2);
    float w0 = e0 * inv, w1 = e1 * inv, w2 = e2 * inv;

    const float* xb = x + (size_t)b * NN_SEQ * DD;
    float s_local[4];
    float sum = 0.f, sumsq = 0.f;

#pragma unroll
    for (int i = 0; i < 4; i++) {
        int d = tid + i * 256;
        float win[49];
#pragma unroll
        for (int j = 0; j < 49; j++) {
            int idx = n + j - 24;
            idx = idx < 0 ? -idx : idx;
            idx = idx >= NN_SEQ ? (2 * NN_SEQ - 2 - idx) : idx;
            win[j] = xb[(size_t)idx * DD + d];
        }
        float t7 = 0.f, t25 = 0.f, t49 = 0.f;
#pragma unroll
        for (int j = 0; j < 7; j++)  t7  += dw7 [d * 7  + j] * win[21 + j];
#pragma unroll
        for (int j = 0; j < 25; j++) t25 += dw25[d * 25 + j] * win[12 + j];
#pragma unroll
        for (int j = 0; j < 49; j++) t49 += dw49[d * 49 + j] * win[j];
        float tr = w0 * t7 + w1 * t25 + w2 * t49;
        float sv = win[24] - tr;
        g_Tr[(size_t)bn * DD + d] = tr;
        g_S [(size_t)bn * DD + d] = sv;
        s_local[i] = sv;
        sum += sv; sumsq += sv * sv;
    }

    __shared__ float sh1[256], sh2[256];
    sh1[tid] = sum; sh2[tid] = sumsq;
    __syncthreads();
    for (int o = 128; o > 0; o >>= 1) {
        if (tid < o) { sh1[tid] += sh1[tid + o]; sh2[tid] += sh2[tid + o]; }
        __syncthreads();
    }
    float mean = sh1[0] * (1.0f / DD);
    float var  = sh2[0] * (1.0f / DD) - mean * mean;
    float rstd = rsqrtf(var + LN_EPS);

#pragma unroll
    for (int i = 0; i < 4; i++) {
        int d = tid + i * 256;
        g_Sn[(size_t)bn * DD + d] = (s_local[i] - mean) * rstd * n1g[d] + n1b[d];
    }
}

// ---------------- generic LN kernel ----------------------------------------
__global__ __launch_bounds__(256) void ln_kernel(
    const float* __restrict__ in, const float* __restrict__ g,
    const float* __restrict__ bta, float* __restrict__ out)
{
    int bn = blockIdx.x;
    int tid = threadIdx.x;
    const float* row = in + (size_t)bn * DD;
    float v[4]; float sum = 0.f, sumsq = 0.f;
#pragma unroll
    for (int i = 0; i < 4; i++) {
        v[i] = row[tid + i * 256];
        sum += v[i]; sumsq += v[i] * v[i];
    }
    __shared__ float sh1[256], sh2[256];
    sh1[tid] = sum; sh2[tid] = sumsq;
    __syncthreads();
    for (int o = 128; o > 0; o >>= 1) {
        if (tid < o) { sh1[tid] += sh1[tid + o]; sh2[tid] += sh2[tid + o]; }
        __syncthreads();
    }
    float mean = sh1[0] * (1.0f / DD);
    float var  = sh2[0] * (1.0f / DD) - mean * mean;
    float rstd = rsqrtf(var + LN_EPS);
#pragma unroll
    for (int i = 0; i < 4; i++) {
        int d = tid + i * 256;
        out[(size_t)bn * DD + d] = (v[i] - mean) * rstd * g[d] + bta[d];
    }
}

// ---------------- tiled fp32 NT GEMM with register double-buffering ---------
// mode 0: C = acc + bias (+ addend)                         (dense)
// mode 1: C[row] = gelu(acc + bias), A rows gathered via rowidx, row<cnt
// mode 2: C[rowidx[row]] += (acc + bias) * rowsw[row], row<cnt (scatter)
#define GTK 16
#define GSA 130
__global__ __launch_bounds__(256, 2) void gemm_nt(
    const float* __restrict__ A, const float* __restrict__ W,
    const float* __restrict__ bias, const float* __restrict__ addend,
    float* __restrict__ C, int M, int Nn, int K, int mode,
    const int* __restrict__ rowidx, const int* __restrict__ cnt_ptr,
    const float* __restrict__ rowsw)
{
    int m0 = blockIdx.y * 128, n0 = blockIdx.x * 128;
    int cval = cnt_ptr ? *cnt_ptr : M;
    if (m0 >= cval) return;

    __shared__ float As[GTK][GSA];
    __shared__ float Ws[GTK][GSA];
    int tid = threadIdx.x;
    int tx = tid & 15, ty = tid >> 4;

    size_t abase[2], wbase[2];
    int srow[2], skc[2];
#pragma unroll
    for (int i = 0; i < 2; i++) {
        int lin = tid + i * 256;
        int row = lin >> 2, kc4 = lin & 3;
        srow[i] = row; skc[i] = kc4;
        int ar = m0 + row;
        if (mode == 1 && rowidx) ar = rowidx[ar < cval ? ar : (cval - 1)];
        abase[i] = (size_t)ar * K;
        wbase[i] = (size_t)(n0 + row) * K;
    }

    float4 ra[2], rw[2];
#pragma unroll
    for (int i = 0; i < 2; i++) {
        ra[i] = *(const float4*)&A[abase[i] + skc[i] * 4];
        rw[i] = *(const float4*)&W[wbase[i] + skc[i] * 4];
    }
#pragma unroll
    for (int i = 0; i < 2; i++) {
        As[skc[i]*4+0][srow[i]] = ra[i].x; As[skc[i]*4+1][srow[i]] = ra[i].y;
        As[skc[i]*4+2][srow[i]] = ra[i].z; As[skc[i]*4+3][srow[i]] = ra[i].w;
        Ws[skc[i]*4+0][srow[i]] = rw[i].x; Ws[skc[i]*4+1][srow[i]] = rw[i].y;
        Ws[skc[i]*4+2][srow[i]] = rw[i].z; Ws[skc[i]*4+3][srow[i]] = rw[i].w;
    }
    __syncthreads();

    float acc[8][8];
#pragma unroll
    for (int i = 0; i < 8; i++)
#pragma unroll
        for (int j = 0; j < 8; j++) acc[i][j] = 0.f;

    for (int k0 = 0; k0 < K; k0 += GTK) {
        bool more = (k0 + GTK) < K;
        if (more) {
#pragma unroll
            for (int i = 0; i < 2; i++) {
                ra[i] = *(const float4*)&A[abase[i] + k0 + GTK + skc[i] * 4];
                rw[i] = *(const float4*)&W[wbase[i] + k0 + GTK + skc[i] * 4];
            }
        }
#pragma unroll
        for (int kk = 0; kk < GTK; kk++) {
            float a[8], bb[8];
#pragma unroll
            for (int i = 0; i < 8; i++) {
                a[i]  = As[kk][ty + 16 * i];
                bb[i] = Ws[kk][tx + 16 * i];
            }
#pragma unroll
            for (int im = 0; im < 8; im++)
#pragma unroll
                for (int in = 0; in < 8; in++)
                    acc[im][in] += a[im] * bb[in];
        }
        if (more) {
            __syncthreads();
#pragma unroll
            for (int i = 0; i < 2; i++) {
                As[skc[i]*4+0][srow[i]] = ra[i].x; As[skc[i]*4+1][srow[i]] = ra[i].y;
                As[skc[i]*4+2][srow[i]] = ra[i].z; As[skc[i]*4+3][srow[i]] = ra[i].w;
                Ws[skc[i]*4+0][srow[i]] = rw[i].x; Ws[skc[i]*4+1][srow[i]] = rw[i].y;
                Ws[skc[i]*4+2][srow[i]] = rw[i].z; Ws[skc[i]*4+3][srow[i]] = rw[i].w;
            }
            __syncthreads();
        }
    }

#pragma unroll
    for (int in_ = 0; in_ < 8; in_++) {
        int col = n0 + tx + 16 * in_;
        float bv = bias ? bias[col] : 0.f;
#pragma unroll
        for (int im = 0; im < 8; im++) {
            int r = m0 + ty + 16 * im;
            float val = acc[im][in_] + bv;
            if (mode == 0) {
                size_t off = (size_t)r * Nn + col;
                if (addend) val += addend[off];
                C[off] = val;
            } else if (mode == 1) {
                if (r < cval)
                    C[(size_t)r * Nn + col] =
                        0.5f * val * (1.0f + erff(val * 0.70710678118f));
            } else {
                if (r < cval) {
                    int tok = rowidx[r];
                    C[(size_t)tok * Nn + col] += val * rowsw[r];
                }
            }
        }
    }
}

// ---------------- attention: 64x64 flash tiles (dynamic smem) ---------------
#define ATP 68
#define ATT_SMEM (4 * 64 * ATP * (int)sizeof(float))
__global__ __launch_bounds__(256) void attn_tile_kernel(
    const float* __restrict__ q, const float* __restrict__ k,
    const float* __restrict__ v, float* __restrict__ y)
{
    extern __shared__ float smem[];
    float (*Qs)[ATP] = (float (*)[ATP])(smem);               // [d][qi]  pre-scaled
    float (*Ks)[ATP] = (float (*)[ATP])(smem + 64 * ATP);    // [d][kj]
    float (*Vs)[ATP] = (float (*)[ATP])(smem + 2 * 64 * ATP);// [kk][d]
    float (*Ps)[ATP] = (float (*)[ATP])(smem + 3 * 64 * ATP);// [kk][qi]

    int bh = blockIdx.x;
    int b = bh / HH, h = bh % HH;
    int q0 = blockIdx.y * 64;
    int tid = threadIdx.x;
    int tx = tid & 15, ty = tid >> 4;
    float slope = exp2f(-0.5f * (float)(h + 1));

    const float* qbase = q + ((size_t)(b * NN_SEQ + q0)) * DD + h * DH;
    for (int i = tid; i < 64 * 16; i += 256) {
        int qi = i >> 4;
        int d4 = (i & 15) * 4;
        float4 val = *(const float4*)&qbase[(size_t)qi * DD + d4];
        Qs[d4 + 0][qi] = val.x * 0.125f;
        Qs[d4 + 1][qi] = val.y * 0.125f;
        Qs[d4 + 2][qi] = val.z * 0.125f;
        Qs[d4 + 3][qi] = val.w * 0.125f;
    }

    float o[4][4];
#pragma unroll
    for (int i = 0; i < 4; i++)
#pragma unroll
        for (int j = 0; j < 4; j++) o[i][j] = 0.f;
    float l[4] = {0.f, 0.f, 0.f, 0.f};
    float m[4] = {-1e30f, -1e30f, -1e30f, -1e30f};

    const float* kbase = k + (size_t)b * NN_SEQ * DD + h * DH;
    const float* vbase = v + (size_t)b * NN_SEQ * DD + h * DH;

    for (int kt = 0; kt < NN_SEQ; kt += 64) {
        __syncthreads();
        for (int i = tid; i < 64 * 16; i += 256) {
            int kk = i >> 4;
            int d4 = (i & 15) * 4;
            float4 kv = *(const float4*)&kbase[(size_t)(kt + kk) * DD + d4];
            Ks[d4 + 0][kk] = kv.x; Ks[d4 + 1][kk] = kv.y;
            Ks[d4 + 2][kk] = kv.z; Ks[d4 + 3][kk] = kv.w;
            float4 vv = *(const float4*)&vbase[(size_t)(kt + kk) * DD + d4];
            *(float4*)&Vs[kk][d4] = vv;
        }
        __syncthreads();

        // S tile: queries ty*4+i, keys tx*4+j
        float s[4][4];
#pragma unroll
        for (int i = 0; i < 4; i++)
#pragma unroll
            for (int j = 0; j < 4; j++) s[i][j] = 0.f;
        for (int d = 0; d < 64; d++) {
            float4 av = *(const float4*)&Qs[d][ty * 4];
            float4 bv = *(const float4*)&Ks[d][tx * 4];
            float a4[4] = {av.x, av.y, av.z, av.w};
            float b4[4] = {bv.x, bv.y, bv.z, bv.w};
#pragma unroll
            for (int i = 0; i < 4; i++)
#pragma unroll
                for (int j = 0; j < 4; j++) s[i][j] += a4[i] * b4[j];
        }

        // ALiBi + online softmax bookkeeping (row groups live in lanes with
        // the same ty across tx: reduce over the 16 tx lanes of the warp-half)
        float c[4];
        float p[4][4];
#pragma unroll
        for (int i = 0; i < 4; i++) {
            int qg = q0 + ty * 4 + i;
            float mx2 = -1e30f;
#pragma unroll
            for (int j = 0; j < 4; j++) {
                int kg = kt + tx * 4 + j;
                int df = kg - qg;
                float dist = df > 0 ? (float)df : 0.f;
                s[i][j] -= slope * dist;
                mx2 = fmaxf(mx2, s[i][j]);
            }
#pragma unroll
            for (int off = 8; off >= 1; off >>= 1)
                mx2 = fmaxf(mx2, __shfl_xor_sync(0xffffffffu, mx2, off));
            float mn = fmaxf(m[i], mx2);
            c[i] = __expf(m[i] - mn);
            m[i] = mn;
            float rs = 0.f;
#pragma unroll
            for (int j = 0; j < 4; j++) {
                p[i][j] = __expf(s[i][j] - mn);
                rs += p[i][j];
            }
#pragma unroll
            for (int off = 8; off >= 1; off >>= 1)
                rs += __shfl_xor_sync(0xffffffffu, rs, off);
            l[i] = l[i] * c[i] + rs;
        }
        // store P transposed: Ps[kj][qi]
#pragma unroll
        for (int j = 0; j < 4; j++) {
            float4 pv = make_float4(p[0][j], p[1][j], p[2][j], p[3][j]);
            *(float4*)&Ps[tx * 4 + j][ty * 4] = pv;
        }
        __syncthreads();

        // O = O*c + P @ V   (output dims tx*4+j)
#pragma unroll
        for (int i = 0; i < 4; i++)
#pragma unroll
            for (int j = 0; j < 4; j++) o[i][j] *= c[i];
        for (int kk = 0; kk < 64; kk++) {
            float4 av = *(const float4*)&Ps[kk][ty * 4];
            float4 bv = *(const float4*)&Vs[kk][tx * 4];
            float a4[4] = {av.x, av.y, av.z, av.w};
            float b4[4] = {bv.x, bv.y, bv.z, bv.w};
#pragma unroll
            for (int i = 0; i < 4; i++)
#pragma unroll
                for (int j = 0; j < 4; j++) o[i][j] += a4[i] * b4[j];
        }
    }

#pragma unroll
    for (int i = 0; i < 4; i++) {
        float invl = 1.0f / l[i];
        float4 ov = make_float4(o[i][0] * invl, o[i][1] * invl,
                                o[i][2] * invl, o[i][3] * invl);
        *(float4*)&y[((size_t)(b * NN_SEQ + q0 + ty * 4 + i)) * DD + h * DH + tx * 4] = ov;
    }
}

// ---------------- router: gates + top-2 weights -----------------------------
__global__ __launch_bounds__(128) void router_kernel(
    const float* __restrict__ xf, const float* __restrict__ rw)
{
    int t = blockIdx.x;
    int lane = threadIdx.x & 31, wrp = threadIdx.x >> 5;
    const float* xr = xf + (size_t)t * DD;
    const float* wr = rw + (size_t)wrp * DD;
    float s = 0.f;
    for (int i = lane; i < DD; i += 32) s += xr[i] * wr[i];
#pragma unroll
    for (int o = 16; o > 0; o >>= 1) s += __shfl_xor_sync(0xffffffffu, s, o);
    __shared__ float sh[4];
    if (lane == 0) sh[wrp] = s;
    __syncthreads();
    if (threadIdx.x == 0) {
        float g[4]; float mx = -1e30f;
#pragma unroll
        for (int e = 0; e < EE; e++) { g[e] = sh[e]; mx = fmaxf(mx, g[e]); }
        float sum = 0.f;
#pragma unroll
        for (int e = 0; e < EE; e++) { g[e] = __expf(g[e] - mx); sum += g[e]; }
        float inv = 1.0f / sum;
#pragma unroll
        for (int e = 0; e < EE; e++) { g[e] *= inv; g_gates[t * EE + e] = g[e]; }
        int i1 = 0;
#pragma unroll
        for (int e = 1; e < EE; e++) if (g[e] > g[i1]) i1 = e;
        int i2 = -1;
#pragma unroll
        for (int e = 0; e < EE; e++)
            if (e != i1 && (i2 < 0 || g[e] > g[i2])) i2 = e;
        float norm = fmaxf(g[i1] + g[i2], 1e-9f);
        float w4[4] = {0.f, 0.f, 0.f, 0.f};
        w4[i1] = g[i1] / norm;
        w4[i2] = g[i2] / norm;
#pragma unroll
        for (int e = 0; e < EE; e++) g_wts[t * EE + e] = w4[e];
    }
}

// ---------------- expert token lists ----------------------------------------
__global__ void clear_cnt_kernel() {
    if (threadIdx.x < EE) g_cnt[threadIdx.x] = 0;
}

__global__ __launch_bounds__(256) void build_lists_kernel() {
    int t = blockIdx.x * 256 + threadIdx.x;
    if (t >= TT) return;
#pragma unroll
    for (int e = 0; e < EE; e++) {
        float w = g_wts[t * EE + e];
        if (w > 0.f) {
            int p = atomicAdd(&g_cnt[e], 1);
            g_list[e * TT + p] = t;
            g_lw[e * TT + p] = w;
        }
    }
}

// ---------------- deterministic aux reduction -------------------------------
__global__ __launch_bounds__(256) void aux_reduce_kernel()
{
    int tid = threadIdx.x;
    float sg[EE] = {0.f, 0.f, 0.f, 0.f};
    float sc[EE] = {0.f, 0.f, 0.f, 0.f};
    for (int t = tid; t < TT; t += 256) {
#pragma unroll
        for (int e = 0; e < EE; e++) {
            sg[e] += g_gates[t * EE + e];
            sc[e] += (g_wts[t * EE + e] > 0.f) ? 1.f : 0.f;
        }
    }
    __shared__ float sh[256];
    float aux = 0.f;
#pragma unroll
    for (int e = 0; e < EE; e++) {
        sh[tid] = sg[e]; __syncthreads();
        for (int o = 128; o > 0; o >>= 1) {
            if (tid < o) sh[tid] += sh[tid + o];
            __syncthreads();
        }
        float tot_g = sh[0]; __syncthreads();
        sh[tid] = sc[e]; __syncthreads();
        for (int o = 128; o > 0; o >>= 1) {
            if (tid < o) sh[tid] += sh[tid + o];
            __syncthreads();
        }
        float tot_c = sh[0]; __syncthreads();
        aux += (tot_g / (float)TT) * (tot_c / (float)TT);
    }
    if (tid == 0) g_auxval[0] = (float)EE * aux;
}

// ---------------- final: + trend depthwise conv(k=5) + aux ------------------
__global__ __launch_bounds__(256) void final_kernel(
    const float* __restrict__ tw, const float* __restrict__ tb,
    float* __restrict__ out, int write_aux)
{
    int bn = blockIdx.x;
    int b = bn / NN_SEQ, n = bn % NN_SEQ;
    int tid = threadIdx.x;
#pragma unroll
    for (int i = 0; i < 4; i++) {
        int d = tid + i * 256;
        float vsum = g_xs[(size_t)bn * DD + d] + tb[d];
#pragma unroll
        for (int j = 0; j < 5; j++) {
            int nn = n - 2 + j;
            if (nn >= 0 && nn < NN_SEQ)
                vsum += tw[d * 5 + j] * g_Tr[((size_t)b * NN_SEQ + nn) * DD + d];
        }
        out[(size_t)bn * DD + d] = vsum;
    }
    if (bn == 0 && tid == 0 && write_aux)
        out[(size_t)BB * NN_SEQ * DD] = g_auxval[0];
}

// ---------------- host orchestration ---------------------------------------
extern "C" void kernel_launch(void* const* d_in, const int* in_sizes, int n_in,
                              void* d_out, int out_size)
{
    const float* x    = (const float*)d_in[0];
    const float* qw   = (const float*)d_in[1];
    const float* qb   = (const float*)d_in[2];
    const float* kw   = (const float*)d_in[3];
    const float* kb   = (const float*)d_in[4];
    const float* vw   = (const float*)d_in[5];
    const float* vb   = (const float*)d_in[6];
    const float* ow   = (const float*)d_in[7];
    const float* ob   = (const float*)d_in[8];
    const float* n1g  = (const float*)d_in[9];
    const float* n1b  = (const float*)d_in[10];
    const float* n2g  = (const float*)d_in[11];
    const float* n2b  = (const float*)d_in[12];
    const float* alpha= (const float*)d_in[13];
    const float* dw7  = (const float*)d_in[14];
    const float* dw25 = (const float*)d_in[15];
    const float* dw49 = (const float*)d_in[16];
    const float* rw   = (const float*)d_in[17];
    const float* ew1  = (const float*)d_in[18];
    const float* eb1  = (const float*)d_in[19];
    const float* ew2  = (const float*)d_in[20];
    const float* eb2  = (const float*)d_in[21];
    const float* tw   = (const float*)d_in[22];
    const float* tb   = (const float*)d_in[23];
    float* out = (float*)d_out;

    float *p_Sn, *p_q, *p_k, *p_v, *p_y, *p_xs, *p_xf, *p_h, *p_S, *p_lw;
    int *p_list, *p_cnt;
    cudaGetSymbolAddress((void**)&p_Sn, g_Sn);
    cudaGetSymbolAddress((void**)&p_q,  g_q);
    cudaGetSymbolAddress((void**)&p_k,  g_k);
    cudaGetSymbolAddress((void**)&p_v,  g_v);
    cudaGetSymbolAddress((void**)&p_y,  g_y);
    cudaGetSymbolAddress((void**)&p_xs, g_xs);
    cudaGetSymbolAddress((void**)&p_xf, g_xf);
    cudaGetSymbolAddress((void**)&p_h,  g_h);
    cudaGetSymbolAddress((void**)&p_S,  g_S);
    cudaGetSymbolAddress((void**)&p_lw,  g_lw);
    cudaGetSymbolAddress((void**)&p_list, g_list);
    cudaGetSymbolAddress((void**)&p_cnt,  g_cnt);

    // attention needs >48KB dynamic smem (attribute set is capture-legal)
    cudaFuncSetAttribute(attn_tile_kernel,
                         cudaFuncAttributeMaxDynamicSharedMemorySize, ATT_SMEM);

    // 1) decomposition + seasonal + LN1
    decomp_ln1_kernel<<<BB * NN_SEQ, 256>>>(x, alpha, dw7, dw25, dw49, n1g, n1b);

    // 2) QKV projections
    dim3 gQ(DD / 128, TT / 128);
    gemm_nt<<<gQ, 256>>>(p_Sn, qw, qb, nullptr, p_q, TT, DD, DD, 0, nullptr, nullptr, nullptr);
    gemm_nt<<<gQ, 256>>>(p_Sn, kw, kb, nullptr, p_k, TT, DD, DD, 0, nullptr, nullptr, nullptr);
    gemm_nt<<<gQ, 256>>>(p_Sn, vw, vb, nullptr, p_v, TT, DD, DD, 0, nullptr, nullptr, nullptr);

    // 3) ALiBi attention (flash tiles)
    attn_tile_kernel<<<dim3(BB * HH, NN_SEQ / 64), 256, ATT_SMEM>>>(p_q, p_k, p_v, p_y);

    // 4) output projection fused with residual: x_s = S + (y @ ow^T + ob)
    gemm_nt<<<gQ, 256>>>(p_y, ow, ob, p_S, p_xs, TT, DD, DD, 0, nullptr, nullptr, nullptr);

    // 5) LN2 -> xf
    ln_kernel<<<BB * NN_SEQ, 256>>>(p_xs, n2g, n2b, p_xf);

    // 6) router, token lists, aux
    router_kernel<<<TT, 128>>>(p_xf, rw);
    clear_cnt_kernel<<<1, 32>>>();
    build_lists_kernel<<<TT / 256, 256>>>();
    aux_reduce_kernel<<<1, 256>>>();

    // 7) sparse MoE: gather -> GEMM1(gelu) -> GEMM2(scatter +=)
    dim3 gE1(MH / 128, TT / 128);
    dim3 gE2(DD / 128, TT / 128);
    for (int e = 0; e < EE; e++) {
        gemm_nt<<<gE1, 256>>>(p_xf, ew1 + (size_t)e * MH * DD, eb1 + (size_t)e * MH,
                              nullptr, p_h, TT, MH, DD, 1,
                              p_list + e * TT, p_cnt + e, nullptr);
        gemm_nt<<<gE2, 256>>>(p_h, ew2 + (size_t)e * DD * MH, eb2 + (size_t)e * DD,
                              nullptr, p_xs, TT, DD, MH, 2,
                              p_list + e * TT, p_cnt + e, p_lw + e * TT);
    }

    // 8) trend conv + final sum + aux scalar
    int write_aux = (out_size > BB * NN_SEQ * DD) ? 1 : 0;
    final_kernel<<<BB * NN_SEQ, 256>>>(tw, tb, out, write_aux);
}

// round 6
// speedup vs baseline: 3.6204x; 3.0202x over previous
#include <cuda_runtime.h>
#include <math.h>
#include <stdint.h>

#define BB 8
#define NN_SEQ 1024
#define DD 1024
#define HH 16
#define DH 64
#define TT (BB * NN_SEQ)      // 8192 tokens
#define EE 4
#define MH 2048
#define LN_EPS 1e-5f

// ---------------- scratch (device globals; no allocations allowed) ----------
__device__ float g_Tr[BB * NN_SEQ * DD];
__device__ float g_S [BB * NN_SEQ * DD];
__device__ float g_Sn[BB * NN_SEQ * DD];
__device__ float g_q [BB * NN_SEQ * DD];
__device__ float g_k [BB * NN_SEQ * DD];
__device__ float g_v [BB * NN_SEQ * DD];
__device__ float g_y [BB * NN_SEQ * DD];
__device__ float g_xs[BB * NN_SEQ * DD];
__device__ float g_xf[BB * NN_SEQ * DD];
__device__ float g_h [TT * MH];
__device__ float g_gates[TT * EE];
__device__ float g_wts  [TT * EE];
__device__ int   g_list [EE * TT];
__device__ float g_lw   [EE * TT];
__device__ int   g_cnt  [EE];
__device__ float g_auxval[1];

// ---------------- kernel 1: decomposition + seasonal + LN1 ------------------
__global__ __launch_bounds__(256) void decomp_ln1_kernel(
    const float* __restrict__ x, const float* __restrict__ alpha,
    const float* __restrict__ dw7, const float* __restrict__ dw25,
    const float* __restrict__ dw49,
    const float* __restrict__ n1g, const float* __restrict__ n1b)
{
    int bn = blockIdx.x;
    int b = bn / NN_SEQ, n = bn % NN_SEQ;
    int tid = threadIdx.x;

    float a0 = alpha[0], a1 = alpha[1], a2 = alpha[2];
    float mx = fmaxf(a0, fmaxf(a1, a2));
    float e0 = __expf(a0 - mx), e1 = __expf(a1 - mx), e2 = __expf(a2 - mx);
    float inv = 1.0f / (e0 + e1 + e2);
    float w0 = e0 * inv, w1 = e1 * inv, w2 = e2 * inv;

    const float* xb = x + (size_t)b * NN_SEQ * DD;
    float s_local[4];
    float sum = 0.f, sumsq = 0.f;

#pragma unroll
    for (int i = 0; i < 4; i++) {
        int d = tid + i * 256;
        float win[49];
#pragma unroll
        for (int j = 0; j < 49; j++) {
            int idx = n + j - 24;
            idx = idx < 0 ? -idx : idx;
            idx = idx >= NN_SEQ ? (2 * NN_SEQ - 2 - idx) : idx;
            win[j] = xb[(size_t)idx * DD + d];
        }
        float t7 = 0.f, t25 = 0.f, t49 = 0.f;
#pragma unroll
        for (int j = 0; j < 7; j++)  t7  += dw7 [d * 7  + j] * win[21 + j];
#pragma unroll
        for (int j = 0; j < 25; j++) t25 += dw25[d * 25 + j] * win[12 + j];
#pragma unroll
        for (int j = 0; j < 49; j++) t49 += dw49[d * 49 + j] * win[j];
        float tr = w0 * t7 + w1 * t25 + w2 * t49;
        float sv = win[24] - tr;
        g_Tr[(size_t)bn * DD + d] = tr;
        g_S [(size_t)bn * DD + d] = sv;
        s_local[i] = sv;
        sum += sv; sumsq += sv * sv;
    }

    __shared__ float sh1[256], sh2[256];
    sh1[tid] = sum; sh2[tid] = sumsq;
    __syncthreads();
    for (int o = 128; o > 0; o >>= 1) {
        if (tid < o) { sh1[tid] += sh1[tid + o]; sh2[tid] += sh2[tid + o]; }
        __syncthreads();
    }
    float mean = sh1[0] * (1.0f / DD);
    float var  = sh2[0] * (1.0f / DD) - mean * mean;
    float rstd = rsqrtf(var + LN_EPS);

#pragma unroll
    for (int i = 0; i < 4; i++) {
        int d = tid + i * 256;
        g_Sn[(size_t)bn * DD + d] = (s_local[i] - mean) * rstd * n1g[d] + n1b[d];
    }
}

// ---------------- generic LN kernel ----------------------------------------
__global__ __launch_bounds__(256) void ln_kernel(
    const float* __restrict__ in, const float* __restrict__ g,
    const float* __restrict__ bta, float* __restrict__ out)
{
    int bn = blockIdx.x;
    int tid = threadIdx.x;
    const float* row = in + (size_t)bn * DD;
    float v[4]; float sum = 0.f, sumsq = 0.f;
#pragma unroll
    for (int i = 0; i < 4; i++) {
        v[i] = row[tid + i * 256];
        sum += v[i]; sumsq += v[i] * v[i];
    }
    __shared__ float sh1[256], sh2[256];
    sh1[tid] = sum; sh2[tid] = sumsq;
    __syncthreads();
    for (int o = 128; o > 0; o >>= 1) {
        if (tid < o) { sh1[tid] += sh1[tid + o]; sh2[tid] += sh2[tid + o]; }
        __syncthreads();
    }
    float mean = sh1[0] * (1.0f / DD);
    float var  = sh2[0] * (1.0f / DD) - mean * mean;
    float rstd = rsqrtf(var + LN_EPS);
#pragma unroll
    for (int i = 0; i < 4; i++) {
        int d = tid + i * 256;
        out[(size_t)bn * DD + d] = (v[i] - mean) * rstd * g[d] + bta[d];
    }
}

// ---------------- TF32 tensor-core NT GEMM ----------------------------------
// C[M,Nn] = A[M,K] @ W[Nn,K]^T  via mma.sync.m16n8k8.tf32
// mode 0: C = acc + bias (+ addend)                         (dense)
// mode 1: C[row] = gelu(acc + bias), A rows gathered via rowidx, row<cnt
// mode 2: C[rowidx[row]] += (acc + bias) * rowsw[row], row<cnt (scatter)
//
// smem k-permutation: k' = (k&3)*8 + (k>>2)  (k in 0..31) so that every
// fragment read is one aligned LDS.64 over 8 consecutive permuted slots.
__device__ __forceinline__ uint32_t f2tf(float f) {
    uint32_t u;
    asm("cvt.rna.tf32.f32 %0, %1;" : "=r"(u) : "f"(f));
    return u;
}

__device__ __forceinline__ void mma_tf32(float* d, const uint32_t* a, const uint32_t* b) {
    asm volatile(
        "mma.sync.aligned.m16n8k8.row.col.f32.tf32.tf32.f32 "
        "{%0,%1,%2,%3}, {%4,%5,%6,%7}, {%8,%9}, {%0,%1,%2,%3};"
        : "+f"(d[0]), "+f"(d[1]), "+f"(d[2]), "+f"(d[3])
        : "r"(a[0]), "r"(a[1]), "r"(a[2]), "r"(a[3]),
          "r"(b[0]), "r"(b[1]));
}

#define TSTR 34   // smem row stride (uint32): even (LDS.64 align) + conflict-free
__global__ __launch_bounds__(256, 2) void gemm_tf32(
    const float* __restrict__ A, const float* __restrict__ W,
    const float* __restrict__ bias, const float* __restrict__ addend,
    float* __restrict__ C, int M, int Nn, int K, int mode,
    const int* __restrict__ rowidx, const int* __restrict__ cnt_ptr,
    const float* __restrict__ rowsw)
{
    int m0 = blockIdx.y * 128, n0 = blockIdx.x * 128;
    int cval = cnt_ptr ? *cnt_ptr : M;
    if (m0 >= cval) return;

    __shared__ __align__(16) uint32_t As[128][TSTR];
    __shared__ __align__(16) uint32_t Ws[128][TSTR];

    int tid = threadIdx.x;
    int lrow = tid >> 1;              // 0..127: tile row this thread loads
    int jbase = (tid & 1) * 4;        // float4 index base (0 or 4)

    int arow = m0 + lrow;
    if (mode == 1 && rowidx) arow = rowidx[arow < cval ? arow : (cval - 1)];
    const float* Aptr = A + (size_t)arow * K;
    const float* Wptr = W + (size_t)(n0 + lrow) * K;

    int lane = tid & 31, wid = tid >> 5;
    int wm = wid >> 2, wn = wid & 3;      // 2 x 4 warp grid; warp tile 64x32
    int g = lane >> 2, c = lane & 3;

    float acc[4][4][4];
#pragma unroll
    for (int i = 0; i < 4; i++)
#pragma unroll
        for (int j = 0; j < 4; j++)
#pragma unroll
            for (int r = 0; r < 4; r++) acc[i][j][r] = 0.f;

    for (int k0 = 0; k0 < K; k0 += 32) {
#pragma unroll
        for (int jj = 0; jj < 4; jj++) {
            int j = jbase + jj;
            float4 av = *(const float4*)&Aptr[k0 + j * 4];
            As[lrow][0 * 8 + j] = f2tf(av.x);
            As[lrow][1 * 8 + j] = f2tf(av.y);
            As[lrow][2 * 8 + j] = f2tf(av.z);
            As[lrow][3 * 8 + j] = f2tf(av.w);
            float4 wv = *(const float4*)&Wptr[k0 + j * 4];
            Ws[lrow][0 * 8 + j] = f2tf(wv.x);
            Ws[lrow][1 * 8 + j] = f2tf(wv.y);
            Ws[lrow][2 * 8 + j] = f2tf(wv.z);
            Ws[lrow][3 * 8 + j] = f2tf(wv.w);
        }
        __syncthreads();

#pragma unroll
        for (int s = 0; s < 4; s++) {
            uint32_t af[4][4], bf[4][2];
#pragma unroll
            for (int mf = 0; mf < 4; mf++) {
                int r = wm * 64 + mf * 16 + g;
                uint2 x = *(const uint2*)&As[r][c * 8 + 2 * s];
                uint2 y = *(const uint2*)&As[r + 8][c * 8 + 2 * s];
                af[mf][0] = x.x; af[mf][2] = x.y;
                af[mf][1] = y.x; af[mf][3] = y.y;
            }
#pragma unroll
            for (int nf = 0; nf < 4; nf++) {
                int cn = wn * 32 + nf * 8 + g;
                uint2 y = *(const uint2*)&Ws[cn][c * 8 + 2 * s];
                bf[nf][0] = y.x; bf[nf][1] = y.y;
            }
#pragma unroll
            for (int mf = 0; mf < 4; mf++)
#pragma unroll
                for (int nf = 0; nf < 4; nf++)
                    mma_tf32(acc[mf][nf], af[mf], bf[nf]);
        }
        __syncthreads();
    }

    // epilogue: c0:(g,2c) c1:(g,2c+1) c2:(g+8,2c) c3:(g+8,2c+1)
#pragma unroll
    for (int mf = 0; mf < 4; mf++) {
#pragma unroll
        for (int half = 0; half < 2; half++) {
            int r = m0 + wm * 64 + mf * 16 + g + half * 8;
#pragma unroll
            for (int nf = 0; nf < 4; nf++) {
                int col = n0 + wn * 32 + nf * 8 + 2 * c;
                float v0 = acc[mf][nf][half * 2 + 0];
                float v1 = acc[mf][nf][half * 2 + 1];
                if (bias) { v0 += bias[col]; v1 += bias[col + 1]; }
                if (mode == 0) {
                    size_t off = (size_t)r * Nn + col;
                    if (addend) {
                        float2 ad = *(const float2*)&addend[off];
                        v0 += ad.x; v1 += ad.y;
                    }
                    float2 ov = make_float2(v0, v1);
                    *(float2*)&C[off] = ov;
                } else if (mode == 1) {
                    if (r < cval) {
                        float2 ov = make_float2(
                            0.5f * v0 * (1.0f + erff(v0 * 0.70710678118f)),
                            0.5f * v1 * (1.0f + erff(v1 * 0.70710678118f)));
                        *(float2*)&C[(size_t)r * Nn + col] = ov;
                    }
                } else {
                    if (r < cval) {
                        int tok = rowidx[r];
                        float w = rowsw[r];
                        size_t off = (size_t)tok * Nn + col;
                        float2 old = *(const float2*)&C[off];
                        float2 ov = make_float2(old.x + v0 * w, old.y + v1 * w);
                        *(float2*)&C[off] = ov;
                    }
                }
            }
        }
    }
}

// ---------------- attention: 64x64 flash tiles (dynamic smem) ---------------
#define ATP 68
#define ATT_SMEM (4 * 64 * ATP * (int)sizeof(float))
__global__ __launch_bounds__(256) void attn_tile_kernel(
    const float* __restrict__ q, const float* __restrict__ k,
    const float* __restrict__ v, float* __restrict__ y)
{
    extern __shared__ float smem[];
    float (*Qs)[ATP] = (float (*)[ATP])(smem);               // [d][qi]  pre-scaled
    float (*Ks)[ATP] = (float (*)[ATP])(smem + 64 * ATP);    // [d][kj]
    float (*Vs)[ATP] = (float (*)[ATP])(smem + 2 * 64 * ATP);// [kk][d]
    float (*Ps)[ATP] = (float (*)[ATP])(smem + 3 * 64 * ATP);// [kk][qi]

    int bh = blockIdx.x;
    int b = bh / HH, h = bh % HH;
    int q0 = blockIdx.y * 64;
    int tid = threadIdx.x;
    int tx = tid & 15, ty = tid >> 4;
    float slope = exp2f(-0.5f * (float)(h + 1));

    const float* qbase = q + ((size_t)(b * NN_SEQ + q0)) * DD + h * DH;
    for (int i = tid; i < 64 * 16; i += 256) {
        int qi = i >> 4;
        int d4 = (i & 15) * 4;
        float4 val = *(const float4*)&qbase[(size_t)qi * DD + d4];
        Qs[d4 + 0][qi] = val.x * 0.125f;
        Qs[d4 + 1][qi] = val.y * 0.125f;
        Qs[d4 + 2][qi] = val.z * 0.125f;
        Qs[d4 + 3][qi] = val.w * 0.125f;
    }

    float o[4][4];
#pragma unroll
    for (int i = 0; i < 4; i++)
#pragma unroll
        for (int j = 0; j < 4; j++) o[i][j] = 0.f;
    float l[4] = {0.f, 0.f, 0.f, 0.f};
    float m[4] = {-1e30f, -1e30f, -1e30f, -1e30f};

    const float* kbase = k + (size_t)b * NN_SEQ * DD + h * DH;
    const float* vbase = v + (size_t)b * NN_SEQ * DD + h * DH;

    for (int kt = 0; kt < NN_SEQ; kt += 64) {
        __syncthreads();
        for (int i = tid; i < 64 * 16; i += 256) {
            int kk = i >> 4;
            int d4 = (i & 15) * 4;
            float4 kv = *(const float4*)&kbase[(size_t)(kt + kk) * DD + d4];
            Ks[d4 + 0][kk] = kv.x; Ks[d4 + 1][kk] = kv.y;
            Ks[d4 + 2][kk] = kv.z; Ks[d4 + 3][kk] = kv.w;
            float4 vv = *(const float4*)&vbase[(size_t)(kt + kk) * DD + d4];
            *(float4*)&Vs[kk][d4] = vv;
        }
        __syncthreads();

        float s[4][4];
#pragma unroll
        for (int i = 0; i < 4; i++)
#pragma unroll
            for (int j = 0; j < 4; j++) s[i][j] = 0.f;
        for (int d = 0; d < 64; d++) {
            float4 av = *(const float4*)&Qs[d][ty * 4];
            float4 bv = *(const float4*)&Ks[d][tx * 4];
            float a4[4] = {av.x, av.y, av.z, av.w};
            float b4[4] = {bv.x, bv.y, bv.z, bv.w};
#pragma unroll
            for (int i = 0; i < 4; i++)
#pragma unroll
                for (int j = 0; j < 4; j++) s[i][j] += a4[i] * b4[j];
        }

        float cc[4];
        float p[4][4];
#pragma unroll
        for (int i = 0; i < 4; i++) {
            int qg = q0 + ty * 4 + i;
            float mx2 = -1e30f;
#pragma unroll
            for (int j = 0; j < 4; j++) {
                int kg = kt + tx * 4 + j;
                int df = kg - qg;
                float dist = df > 0 ? (float)df : 0.f;
                s[i][j] -= slope * dist;
                mx2 = fmaxf(mx2, s[i][j]);
            }
#pragma unroll
            for (int off = 8; off >= 1; off >>= 1)
                mx2 = fmaxf(mx2, __shfl_xor_sync(0xffffffffu, mx2, off));
            float mn = fmaxf(m[i], mx2);
            cc[i] = __expf(m[i] - mn);
            m[i] = mn;
            float rs = 0.f;
#pragma unroll
            for (int j = 0; j < 4; j++) {
                p[i][j] = __expf(s[i][j] - mn);
                rs += p[i][j];
            }
#pragma unroll
            for (int off = 8; off >= 1; off >>= 1)
                rs += __shfl_xor_sync(0xffffffffu, rs, off);
            l[i] = l[i] * cc[i] + rs;
        }
#pragma unroll
        for (int j = 0; j < 4; j++) {
            float4 pv = make_float4(p[0][j], p[1][j], p[2][j], p[3][j]);
            *(float4*)&Ps[tx * 4 + j][ty * 4] = pv;
        }
        __syncthreads();

#pragma unroll
        for (int i = 0; i < 4; i++)
#pragma unroll
            for (int j = 0; j < 4; j++) o[i][j] *= cc[i];
        for (int kk = 0; kk < 64; kk++) {
            float4 av = *(const float4*)&Ps[kk][ty * 4];
            float4 bv = *(const float4*)&Vs[kk][tx * 4];
            float a4[4] = {av.x, av.y, av.z, av.w};
            float b4[4] = {bv.x, bv.y, bv.z, bv.w};
#pragma unroll
            for (int i = 0; i < 4; i++)
#pragma unroll
                for (int j = 0; j < 4; j++) o[i][j] += a4[i] * b4[j];
        }
    }

#pragma unroll
    for (int i = 0; i < 4; i++) {
        float invl = 1.0f / l[i];
        float4 ov = make_float4(o[i][0] * invl, o[i][1] * invl,
                                o[i][2] * invl, o[i][3] * invl);
        *(float4*)&y[((size_t)(b * NN_SEQ + q0 + ty * 4 + i)) * DD + h * DH + tx * 4] = ov;
    }
}

// ---------------- router: gates + top-2 weights -----------------------------
__global__ __launch_bounds__(128) void router_kernel(
    const float* __restrict__ xf, const float* __restrict__ rw)
{
    int t = blockIdx.x;
    int lane = threadIdx.x & 31, wrp = threadIdx.x >> 5;
    const float* xr = xf + (size_t)t * DD;
    const float* wr = rw + (size_t)wrp * DD;
    float s = 0.f;
    for (int i = lane; i < DD; i += 32) s += xr[i] * wr[i];
#pragma unroll
    for (int o = 16; o > 0; o >>= 1) s += __shfl_xor_sync(0xffffffffu, s, o);
    __shared__ float sh[4];
    if (lane == 0) sh[wrp] = s;
    __syncthreads();
    if (threadIdx.x == 0) {
        float g[4]; float mx = -1e30f;
#pragma unroll
        for (int e = 0; e < EE; e++) { g[e] = sh[e]; mx = fmaxf(mx, g[e]); }
        float sum = 0.f;
#pragma unroll
        for (int e = 0; e < EE; e++) { g[e] = __expf(g[e] - mx); sum += g[e]; }
        float inv = 1.0f / sum;
#pragma unroll
        for (int e = 0; e < EE; e++) { g[e] *= inv; g_gates[t * EE + e] = g[e]; }
        int i1 = 0;
#pragma unroll
        for (int e = 1; e < EE; e++) if (g[e] > g[i1]) i1 = e;
        int i2 = -1;
#pragma unroll
        for (int e = 0; e < EE; e++)
            if (e != i1 && (i2 < 0 || g[e] > g[i2])) i2 = e;
        float norm = fmaxf(g[i1] + g[i2], 1e-9f);
        float w4[4] = {0.f, 0.f, 0.f, 0.f};
        w4[i1] = g[i1] / norm;
        w4[i2] = g[i2] / norm;
#pragma unroll
        for (int e = 0; e < EE; e++) g_wts[t * EE + e] = w4[e];
    }
}

// ---------------- expert token lists ----------------------------------------
__global__ void clear_cnt_kernel() {
    if (threadIdx.x < EE) g_cnt[threadIdx.x] = 0;
}

__global__ __launch_bounds__(256) void build_lists_kernel() {
    int t = blockIdx.x * 256 + threadIdx.x;
    if (t >= TT) return;
#pragma unroll
    for (int e = 0; e < EE; e++) {
        float w = g_wts[t * EE + e];
        if (w > 0.f) {
            int p = atomicAdd(&g_cnt[e], 1);
            g_list[e * TT + p] = t;
            g_lw[e * TT + p] = w;
        }
    }
}

// ---------------- deterministic aux reduction -------------------------------
__global__ __launch_bounds__(256) void aux_reduce_kernel()
{
    int tid = threadIdx.x;
    float sg[EE] = {0.f, 0.f, 0.f, 0.f};
    float sc[EE] = {0.f, 0.f, 0.f, 0.f};
    for (int t = tid; t < TT; t += 256) {
#pragma unroll
        for (int e = 0; e < EE; e++) {
            sg[e] += g_gates[t * EE + e];
            sc[e] += (g_wts[t * EE + e] > 0.f) ? 1.f : 0.f;
        }
    }
    __shared__ float sh[256];
    float aux = 0.f;
#pragma unroll
    for (int e = 0; e < EE; e++) {
        sh[tid] = sg[e]; __syncthreads();
        for (int o = 128; o > 0; o >>= 1) {
            if (tid < o) sh[tid] += sh[tid + o];
            __syncthreads();
        }
        float tot_g = sh[0]; __syncthreads();
        sh[tid] = sc[e]; __syncthreads();
        for (int o = 128; o > 0; o >>= 1) {
            if (tid < o) sh[tid] += sh[tid + o];
            __syncthreads();
        }
        float tot_c = sh[0]; __syncthreads();
        aux += (tot_g / (float)TT) * (tot_c / (float)TT);
    }
    if (tid == 0) g_auxval[0] = (float)EE * aux;
}

// ---------------- final: + trend depthwise conv(k=5) + aux ------------------
__global__ __launch_bounds__(256) void final_kernel(
    const float* __restrict__ tw, const float* __restrict__ tb,
    float* __restrict__ out, int write_aux)
{
    int bn = blockIdx.x;
    int b = bn / NN_SEQ, n = bn % NN_SEQ;
    int tid = threadIdx.x;
#pragma unroll
    for (int i = 0; i < 4; i++) {
        int d = tid + i * 256;
        float vsum = g_xs[(size_t)bn * DD + d] + tb[d];
#pragma unroll
        for (int j = 0; j < 5; j++) {
            int nn = n - 2 + j;
            if (nn >= 0 && nn < NN_SEQ)
                vsum += tw[d * 5 + j] * g_Tr[((size_t)b * NN_SEQ + nn) * DD + d];
        }
        out[(size_t)bn * DD + d] = vsum;
    }
    if (bn == 0 && tid == 0 && write_aux)
        out[(size_t)BB * NN_SEQ * DD] = g_auxval[0];
}

// ---------------- host orchestration ---------------------------------------
extern "C" void kernel_launch(void* const* d_in, const int* in_sizes, int n_in,
                              void* d_out, int out_size)
{
    const float* x    = (const float*)d_in[0];
    const float* qw   = (const float*)d_in[1];
    const float* qb   = (const float*)d_in[2];
    const float* kw   = (const float*)d_in[3];
    const float* kb   = (const float*)d_in[4];
    const float* vw   = (const float*)d_in[5];
    const float* vb   = (const float*)d_in[6];
    const float* ow   = (const float*)d_in[7];
    const float* ob   = (const float*)d_in[8];
    const float* n1g  = (const float*)d_in[9];
    const float* n1b  = (const float*)d_in[10];
    const float* n2g  = (const float*)d_in[11];
    const float* n2b  = (const float*)d_in[12];
    const float* alpha= (const float*)d_in[13];
    const float* dw7  = (const float*)d_in[14];
    const float* dw25 = (const float*)d_in[15];
    const float* dw49 = (const float*)d_in[16];
    const float* rw   = (const float*)d_in[17];
    const float* ew1  = (const float*)d_in[18];
    const float* eb1  = (const float*)d_in[19];
    const float* ew2  = (const float*)d_in[20];
    const float* eb2  = (const float*)d_in[21];
    const float* tw   = (const float*)d_in[22];
    const float* tb   = (const float*)d_in[23];
    float* out = (float*)d_out;

    float *p_Sn, *p_q, *p_k, *p_v, *p_y, *p_xs, *p_xf, *p_h, *p_S, *p_lw;
    int *p_list, *p_cnt;
    cudaGetSymbolAddress((void**)&p_Sn, g_Sn);
    cudaGetSymbolAddress((void**)&p_q,  g_q);
    cudaGetSymbolAddress((void**)&p_k,  g_k);
    cudaGetSymbolAddress((void**)&p_v,  g_v);
    cudaGetSymbolAddress((void**)&p_y,  g_y);
    cudaGetSymbolAddress((void**)&p_xs, g_xs);
    cudaGetSymbolAddress((void**)&p_xf, g_xf);
    cudaGetSymbolAddress((void**)&p_h,  g_h);
    cudaGetSymbolAddress((void**)&p_S,  g_S);
    cudaGetSymbolAddress((void**)&p_lw,  g_lw);
    cudaGetSymbolAddress((void**)&p_list, g_list);
    cudaGetSymbolAddress((void**)&p_cnt,  g_cnt);

    cudaFuncSetAttribute(attn_tile_kernel,
                         cudaFuncAttributeMaxDynamicSharedMemorySize, ATT_SMEM);

    // 1) decomposition + seasonal + LN1
    decomp_ln1_kernel<<<BB * NN_SEQ, 256>>>(x, alpha, dw7, dw25, dw49, n1g, n1b);

    // 2) QKV projections (TF32 tensor cores)
    dim3 gQ(DD / 128, TT / 128);
    gemm_tf32<<<gQ, 256>>>(p_Sn, qw, qb, nullptr, p_q, TT, DD, DD, 0, nullptr, nullptr, nullptr);
    gemm_tf32<<<gQ, 256>>>(p_Sn, kw, kb, nullptr, p_k, TT, DD, DD, 0, nullptr, nullptr, nullptr);
    gemm_tf32<<<gQ, 256>>>(p_Sn, vw, vb, nullptr, p_v, TT, DD, DD, 0, nullptr, nullptr, nullptr);

    // 3) ALiBi attention (flash tiles, fp32)
    attn_tile_kernel<<<dim3(BB * HH, NN_SEQ / 64), 256, ATT_SMEM>>>(p_q, p_k, p_v, p_y);

    // 4) output projection fused with residual: x_s = S + (y @ ow^T + ob)
    gemm_tf32<<<gQ, 256>>>(p_y, ow, ob, p_S, p_xs, TT, DD, DD, 0, nullptr, nullptr, nullptr);

    // 5) LN2 -> xf
    ln_kernel<<<BB * NN_SEQ, 256>>>(p_xs, n2g, n2b, p_xf);

    // 6) router, token lists, aux
    router_kernel<<<TT, 128>>>(p_xf, rw);
    clear_cnt_kernel<<<1, 32>>>();
    build_lists_kernel<<<TT / 256, 256>>>();
    aux_reduce_kernel<<<1, 256>>>();

    // 7) sparse MoE: gather -> GEMM1(gelu) -> GEMM2(scatter +=)
    dim3 gE1(MH / 128, TT / 128);
    dim3 gE2(DD / 128, TT / 128);
    for (int e = 0; e < EE; e++) {
        gemm_tf32<<<gE1, 256>>>(p_xf, ew1 + (size_t)e * MH * DD, eb1 + (size_t)e * MH,
                                nullptr, p_h, TT, MH, DD, 1,
                                p_list + e * TT, p_cnt + e, nullptr);
        gemm_tf32<<<gE2, 256>>>(p_h, ew2 + (size_t)e * DD * MH, eb2 + (size_t)e * DD,
                                nullptr, p_xs, TT, DD, MH, 2,
                                p_list + e * TT, p_cnt + e, p_lw + e * TT);
    }

    // 8) trend conv + final sum + aux scalar
    int write_aux = (out_size > BB * NN_SEQ * DD) ? 1 : 0;
    final_kernel<<<BB * NN_SEQ, 256>>>(tw, tb, out, write_aux);
}

// round 7
// speedup vs baseline: 4.0671x; 1.1234x over previous
#include <cuda_runtime.h>
#include <math.h>
#include <stdint.h>

#define BB 8
#define NN_SEQ 1024
#define DD 1024
#define HH 16
#define DH 64
#define TT (BB * NN_SEQ)      // 8192 tokens
#define EE 4
#define MH 2048
#define LN_EPS 1e-5f

// ---------------- scratch (device globals; no allocations allowed) ----------
__device__ float g_Tr[BB * NN_SEQ * DD];
__device__ float g_S [BB * NN_SEQ * DD];
__device__ float g_Sn[BB * NN_SEQ * DD];   // tf32-rounded at write
__device__ float g_q [BB * NN_SEQ * DD];
__device__ float g_k [BB * NN_SEQ * DD];
__device__ float g_v [BB * NN_SEQ * DD];
__device__ float g_y [BB * NN_SEQ * DD];   // tf32-rounded at write
__device__ float g_xs[BB * NN_SEQ * DD];
__device__ float g_xf[BB * NN_SEQ * DD];   // exact (router input)
__device__ float g_xfr[BB * NN_SEQ * DD];  // tf32-rounded copy (GEMM input)
__device__ float g_h [TT * MH];            // tf32-rounded at write
__device__ float g_gates[TT * EE];
__device__ float g_wts  [TT * EE];
__device__ int   g_list [EE * TT];
__device__ float g_lw   [EE * TT];
__device__ int   g_cnt  [EE];
__device__ float g_auxval[1];
// pre-rounded weights: qw,kw,vw,ow (4 x 1M), ew1 (4 x 2M), ew2 (4 x 2M)
#define WR_Q  0
#define WR_K  (DD * DD)
#define WR_V  (2 * DD * DD)
#define WR_O  (3 * DD * DD)
#define WR_E1 (4 * DD * DD)
#define WR_E2 (4 * DD * DD + EE * MH * DD)
#define WR_TOTAL (4 * DD * DD + 2 * EE * MH * DD)
__device__ float g_wr[WR_TOTAL];

// ---------------- tf32 rounding helpers -------------------------------------
__device__ __forceinline__ uint32_t f2tf(float f) {
    uint32_t u;
    asm("cvt.rna.tf32.f32 %0, %1;" : "=r"(u) : "f"(f));
    return u;
}
__device__ __forceinline__ float tf32r(float f) {
    return __uint_as_float(f2tf(f));
}

__global__ __launch_bounds__(256) void round_tf32_kernel(
    const float* __restrict__ src, float* __restrict__ dst, int n)
{
    int i = (blockIdx.x * 256 + threadIdx.x) * 4;
    if (i < n) {
        float4 v = *(const float4*)&src[i];
        v.x = tf32r(v.x); v.y = tf32r(v.y);
        v.z = tf32r(v.z); v.w = tf32r(v.w);
        *(float4*)&dst[i] = v;
    }
}

// ---------------- kernel 1: decomposition + seasonal + LN1 ------------------
__global__ __launch_bounds__(256) void decomp_ln1_kernel(
    const float* __restrict__ x, const float* __restrict__ alpha,
    const float* __restrict__ dw7, const float* __restrict__ dw25,
    const float* __restrict__ dw49,
    const float* __restrict__ n1g, const float* __restrict__ n1b)
{
    int bn = blockIdx.x;
    int b = bn / NN_SEQ, n = bn % NN_SEQ;
    int tid = threadIdx.x;

    float a0 = alpha[0], a1 = alpha[1], a2 = alpha[2];
    float mx = fmaxf(a0, fmaxf(a1, a2));
    float e0 = __expf(a0 - mx), e1 = __expf(a1 - mx), e2 = __expf(a2 - mx);
    float inv = 1.0f / (e0 + e1 + e2);
    float w0 = e0 * inv, w1 = e1 * inv, w2 = e2 * inv;

    const float* xb = x + (size_t)b * NN_SEQ * DD;
    float s_local[4];
    float sum = 0.f, sumsq = 0.f;

#pragma unroll
    for (int i = 0; i < 4; i++) {
        int d = tid + i * 256;
        float win[49];
#pragma unroll
        for (int j = 0; j < 49; j++) {
            int idx = n + j - 24;
            idx = idx < 0 ? -idx : idx;
            idx = idx >= NN_SEQ ? (2 * NN_SEQ - 2 - idx) : idx;
            win[j] = xb[(size_t)idx * DD + d];
        }
        float t7 = 0.f, t25 = 0.f, t49 = 0.f;
#pragma unroll
        for (int j = 0; j < 7; j++)  t7  += dw7 [d * 7  + j] * win[21 + j];
#pragma unroll
        for (int j = 0; j < 25; j++) t25 += dw25[d * 25 + j] * win[12 + j];
#pragma unroll
        for (int j = 0; j < 49; j++) t49 += dw49[d * 49 + j] * win[j];
        float tr = w0 * t7 + w1 * t25 + w2 * t49;
        float sv = win[24] - tr;
        g_Tr[(size_t)bn * DD + d] = tr;
        g_S [(size_t)bn * DD + d] = sv;
        s_local[i] = sv;
        sum += sv; sumsq += sv * sv;
    }

    __shared__ float sh1[256], sh2[256];
    sh1[tid] = sum; sh2[tid] = sumsq;
    __syncthreads();
    for (int o = 128; o > 0; o >>= 1) {
        if (tid < o) { sh1[tid] += sh1[tid + o]; sh2[tid] += sh2[tid + o]; }
        __syncthreads();
    }
    float mean = sh1[0] * (1.0f / DD);
    float var  = sh2[0] * (1.0f / DD) - mean * mean;
    float rstd = rsqrtf(var + LN_EPS);

#pragma unroll
    for (int i = 0; i < 4; i++) {
        int d = tid + i * 256;
        g_Sn[(size_t)bn * DD + d] =
            tf32r((s_local[i] - mean) * rstd * n1g[d] + n1b[d]);
    }
}

// ---------------- generic LN kernel (optional rounded second output) --------
__global__ __launch_bounds__(256) void ln_kernel(
    const float* __restrict__ in, const float* __restrict__ g,
    const float* __restrict__ bta, float* __restrict__ out,
    float* __restrict__ out_r)
{
    int bn = blockIdx.x;
    int tid = threadIdx.x;
    const float* row = in + (size_t)bn * DD;
    float v[4]; float sum = 0.f, sumsq = 0.f;
#pragma unroll
    for (int i = 0; i < 4; i++) {
        v[i] = row[tid + i * 256];
        sum += v[i]; sumsq += v[i] * v[i];
    }
    __shared__ float sh1[256], sh2[256];
    sh1[tid] = sum; sh2[tid] = sumsq;
    __syncthreads();
    for (int o = 128; o > 0; o >>= 1) {
        if (tid < o) { sh1[tid] += sh1[tid + o]; sh2[tid] += sh2[tid + o]; }
        __syncthreads();
    }
    float mean = sh1[0] * (1.0f / DD);
    float var  = sh2[0] * (1.0f / DD) - mean * mean;
    float rstd = rsqrtf(var + LN_EPS);
#pragma unroll
    for (int i = 0; i < 4; i++) {
        int d = tid + i * 256;
        float ov = (v[i] - mean) * rstd * g[d] + bta[d];
        out[(size_t)bn * DD + d] = ov;
        if (out_r) out_r[(size_t)bn * DD + d] = tf32r(ov);
    }
}

// ---------------- TF32 tensor-core NT GEMM, cp.async 2-stage pipeline -------
// All operands MUST be pre-rounded to tf32 (low 13 mantissa bits zero).
// C[M,Nn] = A[M,K] @ W[Nn,K]^T
// mode 0: C = acc + bias (+ addend)                         (dense)
// mode 1: C[row] = tf32r(gelu(acc + bias)), rows gathered via rowidx, row<cnt
// mode 2: C[rowidx[row]] += (acc + bias) * rowsw[row], row<cnt (scatter)
//
// smem: identity row layout (32 floats/row), 16B-chunk XOR swizzle
//   addr(r,k) = r*32 + ((k>>2) ^ (r&7))*4 + (k&3)
// Fragment rows always satisfy r&7 == g  -> conflict-free LDS.32.
__device__ __forceinline__ void mma_tf32(float* d, const uint32_t* a, const uint32_t* b) {
    asm volatile(
        "mma.sync.aligned.m16n8k8.row.col.f32.tf32.tf32.f32 "
        "{%0,%1,%2,%3}, {%4,%5,%6,%7}, {%8,%9}, {%0,%1,%2,%3};"
        : "+f"(d[0]), "+f"(d[1]), "+f"(d[2]), "+f"(d[3])
        : "r"(a[0]), "r"(a[1]), "r"(a[2]), "r"(a[3]),
          "r"(b[0]), "r"(b[1]));
}

__device__ __forceinline__ void cpa16(float* dst, const float* src) {
    uint32_t d = (uint32_t)__cvta_generic_to_shared(dst);
    asm volatile("cp.async.cg.shared.global [%0], [%1], 16;\n" :: "r"(d), "l"(src));
}

#define GSMEM (2 * 4096 * 2 * (int)sizeof(float))   // 2 stages x (A 16KB + W 16KB)
__global__ __launch_bounds__(256, 2) void gemm_tf32(
    const float* __restrict__ A, const float* __restrict__ W,
    const float* __restrict__ bias, const float* __restrict__ addend,
    float* __restrict__ C, int M, int Nn, int K, int mode,
    const int* __restrict__ rowidx, const int* __restrict__ cnt_ptr,
    const float* __restrict__ rowsw)
{
    int m0 = blockIdx.y * 128, n0 = blockIdx.x * 128;
    int cval = cnt_ptr ? *cnt_ptr : M;
    if (m0 >= cval) return;

    extern __shared__ float sm[];
    float* Abuf = sm;               // [2][4096]
    float* Wbuf = sm + 2 * 4096;    // [2][4096]

    int tid = threadIdx.x;
    int lrow = tid >> 1;            // 0..127
    int cbase = (tid & 1) * 4;      // chunk base: 0 or 4

    int arow = m0 + lrow;
    if (mode == 1 && rowidx) arow = rowidx[arow < cval ? arow : (cval - 1)];
    const float* Aptr = A + (size_t)arow * K + cbase * 4;
    const float* Wptr = W + (size_t)(n0 + lrow) * K + cbase * 4;

    // this thread's 4 smem slot offsets (floats), chunk-swizzled
    int dsts[4];
#pragma unroll
    for (int j = 0; j < 4; j++)
        dsts[j] = lrow * 32 + ((cbase + j) ^ (lrow & 7)) * 4;

    int lane = tid & 31, wid = tid >> 5;
    int wm = wid >> 2, wn = wid & 3;      // 2 x 4 warp grid; warp tile 64x32
    int g = lane >> 2, c = lane & 3;

    float acc[4][4][4];
#pragma unroll
    for (int i = 0; i < 4; i++)
#pragma unroll
        for (int j = 0; j < 4; j++)
#pragma unroll
            for (int r = 0; r < 4; r++) acc[i][j][r] = 0.f;

    int nk = K / 32;
    // prologue: stage 0
#pragma unroll
    for (int j = 0; j < 4; j++) {
        cpa16(Abuf + dsts[j], Aptr + j * 4);
        cpa16(Wbuf + dsts[j], Wptr + j * 4);
    }
    asm volatile("cp.async.commit_group;\n" ::);

    for (int it = 0; it < nk; it++) {
        bool pre = (it + 1) < nk;
        if (pre) {
            int st = (it + 1) & 1;
            int k0 = (it + 1) * 32;
#pragma unroll
            for (int j = 0; j < 4; j++) {
                cpa16(Abuf + st * 4096 + dsts[j], Aptr + k0 + j * 4);
                cpa16(Wbuf + st * 4096 + dsts[j], Wptr + k0 + j * 4);
            }
            asm volatile("cp.async.commit_group;\n" ::);
            asm volatile("cp.async.wait_group 1;\n" ::);
        } else {
            asm volatile("cp.async.wait_group 0;\n" ::);
        }
        __syncthreads();

        const float* Ab = Abuf + (it & 1) * 4096;
        const float* Wb = Wbuf + (it & 1) * 4096;
#pragma unroll
        for (int s = 0; s < 4; s++) {
            int sw0 = ((2 * s) ^ g) * 4 + c;
            int sw1 = ((2 * s + 1) ^ g) * 4 + c;
            uint32_t af[4][4], bf[4][2];
#pragma unroll
            for (int mf = 0; mf < 4; mf++) {
                const float* pa = Ab + (wm * 64 + mf * 16 + g) * 32;
                af[mf][0] = __float_as_uint(pa[sw0]);
                af[mf][1] = __float_as_uint(pa[8 * 32 + sw0]);
                af[mf][2] = __float_as_uint(pa[sw1]);
                af[mf][3] = __float_as_uint(pa[8 * 32 + sw1]);
            }
#pragma unroll
            for (int nf = 0; nf < 4; nf++) {
                const float* pw = Wb + (wn * 32 + nf * 8 + g) * 32;
                bf[nf][0] = __float_as_uint(pw[sw0]);
                bf[nf][1] = __float_as_uint(pw[sw1]);
            }
#pragma unroll
            for (int mf = 0; mf < 4; mf++)
#pragma unroll
                for (int nf = 0; nf < 4; nf++)
                    mma_tf32(acc[mf][nf], af[mf], bf[nf]);
        }
        __syncthreads();
    }

    // epilogue: c0:(g,2c) c1:(g,2c+1) c2:(g+8,2c) c3:(g+8,2c+1)
#pragma unroll
    for (int mf = 0; mf < 4; mf++) {
#pragma unroll
        for (int half = 0; half < 2; half++) {
            int r = m0 + wm * 64 + mf * 16 + g + half * 8;
#pragma unroll
            for (int nf = 0; nf < 4; nf++) {
                int col = n0 + wn * 32 + nf * 8 + 2 * c;
                float v0 = acc[mf][nf][half * 2 + 0];
                float v1 = acc[mf][nf][half * 2 + 1];
                if (bias) { v0 += bias[col]; v1 += bias[col + 1]; }
                if (mode == 0) {
                    size_t off = (size_t)r * Nn + col;
                    if (addend) {
                        float2 ad = *(const float2*)&addend[off];
                        v0 += ad.x; v1 += ad.y;
                    }
                    float2 ov = make_float2(v0, v1);
                    *(float2*)&C[off] = ov;
                } else if (mode == 1) {
                    if (r < cval) {
                        float g0 = 0.5f * v0 * (1.0f + erff(v0 * 0.70710678118f));
                        float g1 = 0.5f * v1 * (1.0f + erff(v1 * 0.70710678118f));
                        float2 ov = make_float2(tf32r(g0), tf32r(g1));
                        *(float2*)&C[(size_t)r * Nn + col] = ov;
                    }
                } else {
                    if (r < cval) {
                        int tok = rowidx[r];
                        float w = rowsw[r];
                        size_t off = (size_t)tok * Nn + col;
                        float2 old = *(const float2*)&C[off];
                        float2 ov = make_float2(old.x + v0 * w, old.y + v1 * w);
                        *(float2*)&C[off] = ov;
                    }
                }
            }
        }
    }
}

// ---------------- attention: 64x64 flash tiles (dynamic smem) ---------------
#define ATP 68
#define ATT_SMEM (4 * 64 * ATP * (int)sizeof(float))
__global__ __launch_bounds__(256) void attn_tile_kernel(
    const float* __restrict__ q, const float* __restrict__ k,
    const float* __restrict__ v, float* __restrict__ y)
{
    extern __shared__ float smem[];
    float (*Qs)[ATP] = (float (*)[ATP])(smem);               // [d][qi]  pre-scaled
    float (*Ks)[ATP] = (float (*)[ATP])(smem + 64 * ATP);    // [d][kj]
    float (*Vs)[ATP] = (float (*)[ATP])(smem + 2 * 64 * ATP);// [kk][d]
    float (*Ps)[ATP] = (float (*)[ATP])(smem + 3 * 64 * ATP);// [kk][qi]

    int bh = blockIdx.x;
    int b = bh / HH, h = bh % HH;
    int q0 = blockIdx.y * 64;
    int tid = threadIdx.x;
    int tx = tid & 15, ty = tid >> 4;
    float slope = exp2f(-0.5f * (float)(h + 1));

    const float* qbase = q + ((size_t)(b * NN_SEQ + q0)) * DD + h * DH;
    for (int i = tid; i < 64 * 16; i += 256) {
        int qi = i >> 4;
        int d4 = (i & 15) * 4;
        float4 val = *(const float4*)&qbase[(size_t)qi * DD + d4];
        Qs[d4 + 0][qi] = val.x * 0.125f;
        Qs[d4 + 1][qi] = val.y * 0.125f;
        Qs[d4 + 2][qi] = val.z * 0.125f;
        Qs[d4 + 3][qi] = val.w * 0.125f;
    }

    float o[4][4];
#pragma unroll
    for (int i = 0; i < 4; i++)
#pragma unroll
        for (int j = 0; j < 4; j++) o[i][j] = 0.f;
    float l[4] = {0.f, 0.f, 0.f, 0.f};
    float m[4] = {-1e30f, -1e30f, -1e30f, -1e30f};

    const float* kbase = k + (size_t)b * NN_SEQ * DD + h * DH;
    const float* vbase = v + (size_t)b * NN_SEQ * DD + h * DH;

    for (int kt = 0; kt < NN_SEQ; kt += 64) {
        __syncthreads();
        for (int i = tid; i < 64 * 16; i += 256) {
            int kk = i >> 4;
            int d4 = (i & 15) * 4;
            float4 kv = *(const float4*)&kbase[(size_t)(kt + kk) * DD + d4];
            Ks[d4 + 0][kk] = kv.x; Ks[d4 + 1][kk] = kv.y;
            Ks[d4 + 2][kk] = kv.z; Ks[d4 + 3][kk] = kv.w;
            float4 vv = *(const float4*)&vbase[(size_t)(kt + kk) * DD + d4];
            *(float4*)&Vs[kk][d4] = vv;
        }
        __syncthreads();

        float s[4][4];
#pragma unroll
        for (int i = 0; i < 4; i++)
#pragma unroll
            for (int j = 0; j < 4; j++) s[i][j] = 0.f;
        for (int d = 0; d < 64; d++) {
            float4 av = *(const float4*)&Qs[d][ty * 4];
            float4 bv = *(const float4*)&Ks[d][tx * 4];
            float a4[4] = {av.x, av.y, av.z, av.w};
            float b4[4] = {bv.x, bv.y, bv.z, bv.w};
#pragma unroll
            for (int i = 0; i < 4; i++)
#pragma unroll
                for (int j = 0; j < 4; j++) s[i][j] += a4[i] * b4[j];
        }

        float cc[4];
        float p[4][4];
#pragma unroll
        for (int i = 0; i < 4; i++) {
            int qg = q0 + ty * 4 + i;
            float mx2 = -1e30f;
#pragma unroll
            for (int j = 0; j < 4; j++) {
                int kg = kt + tx * 4 + j;
                int df = kg - qg;
                float dist = df > 0 ? (float)df : 0.f;
                s[i][j] -= slope * dist;
                mx2 = fmaxf(mx2, s[i][j]);
            }
#pragma unroll
            for (int off = 8; off >= 1; off >>= 1)
                mx2 = fmaxf(mx2, __shfl_xor_sync(0xffffffffu, mx2, off));
            float mn = fmaxf(m[i], mx2);
            cc[i] = __expf(m[i] - mn);
            m[i] = mn;
            float rs = 0.f;
#pragma unroll
            for (int j = 0; j < 4; j++) {
                p[i][j] = __expf(s[i][j] - mn);
                rs += p[i][j];
            }
#pragma unroll
            for (int off = 8; off >= 1; off >>= 1)
                rs += __shfl_xor_sync(0xffffffffu, rs, off);
            l[i] = l[i] * cc[i] + rs;
        }
#pragma unroll
        for (int j = 0; j < 4; j++) {
            float4 pv = make_float4(p[0][j], p[1][j], p[2][j], p[3][j]);
            *(float4*)&Ps[tx * 4 + j][ty * 4] = pv;
        }
        __syncthreads();

#pragma unroll
        for (int i = 0; i < 4; i++)
#pragma unroll
            for (int j = 0; j < 4; j++) o[i][j] *= cc[i];
        for (int kk = 0; kk < 64; kk++) {
            float4 av = *(const float4*)&Ps[kk][ty * 4];
            float4 bv = *(const float4*)&Vs[kk][tx * 4];
            float a4[4] = {av.x, av.y, av.z, av.w};
            float b4[4] = {bv.x, bv.y, bv.z, bv.w};
#pragma unroll
            for (int i = 0; i < 4; i++)
#pragma unroll
                for (int j = 0; j < 4; j++) o[i][j] += a4[i] * b4[j];
        }
    }

#pragma unroll
    for (int i = 0; i < 4; i++) {
        float invl = 1.0f / l[i];
        float4 ov = make_float4(tf32r(o[i][0] * invl), tf32r(o[i][1] * invl),
                                tf32r(o[i][2] * invl), tf32r(o[i][3] * invl));
        *(float4*)&y[((size_t)(b * NN_SEQ + q0 + ty * 4 + i)) * DD + h * DH + tx * 4] = ov;
    }
}

// ---------------- router: gates + top-2 weights -----------------------------
__global__ __launch_bounds__(128) void router_kernel(
    const float* __restrict__ xf, const float* __restrict__ rw)
{
    int t = blockIdx.x;
    int lane = threadIdx.x & 31, wrp = threadIdx.x >> 5;
    const float* xr = xf + (size_t)t * DD;
    const float* wr = rw + (size_t)wrp * DD;
    float s = 0.f;
    for (int i = lane; i < DD; i += 32) s += xr[i] * wr[i];
#pragma unroll
    for (int o = 16; o > 0; o >>= 1) s += __shfl_xor_sync(0xffffffffu, s, o);
    __shared__ float sh[4];
    if (lane == 0) sh[wrp] = s;
    __syncthreads();
    if (threadIdx.x == 0) {
        float g[4]; float mx = -1e30f;
#pragma unroll
        for (int e = 0; e < EE; e++) { g[e] = sh[e]; mx = fmaxf(mx, g[e]); }
        float sum = 0.f;
#pragma unroll
        for (int e = 0; e < EE; e++) { g[e] = __expf(g[e] - mx); sum += g[e]; }
        float inv = 1.0f / sum;
#pragma unroll
        for (int e = 0; e < EE; e++) { g[e] *= inv; g_gates[t * EE + e] = g[e]; }
        int i1 = 0;
#pragma unroll
        for (int e = 1; e < EE; e++) if (g[e] > g[i1]) i1 = e;
        int i2 = -1;
#pragma unroll
        for (int e = 0; e < EE; e++)
            if (e != i1 && (i2 < 0 || g[e] > g[i2])) i2 = e;
        float norm = fmaxf(g[i1] + g[i2], 1e-9f);
        float w4[4] = {0.f, 0.f, 0.f, 0.f};
        w4[i1] = g[i1] / norm;
        w4[i2] = g[i2] / norm;
#pragma unroll
        for (int e = 0; e < EE; e++) g_wts[t * EE + e] = w4[e];
    }
}

// ---------------- expert token lists ----------------------------------------
__global__ void clear_cnt_kernel() {
    if (threadIdx.x < EE) g_cnt[threadIdx.x] = 0;
}

__global__ __launch_bounds__(256) void build_lists_kernel() {
    int t = blockIdx.x * 256 + threadIdx.x;
    if (t >= TT) return;
#pragma unroll
    for (int e = 0; e < EE; e++) {
        float w = g_wts[t * EE + e];
        if (w > 0.f) {
            int p = atomicAdd(&g_cnt[e], 1);
            g_list[e * TT + p] = t;
            g_lw[e * TT + p] = w;
        }
    }
}

// ---------------- deterministic aux reduction -------------------------------
__global__ __launch_bounds__(256) void aux_reduce_kernel()
{
    int tid = threadIdx.x;
    float sg[EE] = {0.f, 0.f, 0.f, 0.f};
    float sc[EE] = {0.f, 0.f, 0.f, 0.f};
    for (int t = tid; t < TT; t += 256) {
#pragma unroll
        for (int e = 0; e < EE; e++) {
            sg[e] += g_gates[t * EE + e];
            sc[e] += (g_wts[t * EE + e] > 0.f) ? 1.f : 0.f;
        }
    }
    __shared__ float sh[256];
    float aux = 0.f;
#pragma unroll
    for (int e = 0; e < EE; e++) {
        sh[tid] = sg[e]; __syncthreads();
        for (int o = 128; o > 0; o >>= 1) {
            if (tid < o) sh[tid] += sh[tid + o];
            __syncthreads();
        }
        float tot_g = sh[0]; __syncthreads();
        sh[tid] = sc[e]; __syncthreads();
        for (int o = 128; o > 0; o >>= 1) {
            if (tid < o) sh[tid] += sh[tid + o];
            __syncthreads();
        }
        float tot_c = sh[0]; __syncthreads();
        aux += (tot_g / (float)TT) * (tot_c / (float)TT);
    }
    if (tid == 0) g_auxval[0] = (float)EE * aux;
}

// ---------------- final: + trend depthwise conv(k=5) + aux ------------------
__global__ __launch_bounds__(256) void final_kernel(
    const float* __restrict__ tw, const float* __restrict__ tb,
    float* __restrict__ out, int write_aux)
{
    int bn = blockIdx.x;
    int b = bn / NN_SEQ, n = bn % NN_SEQ;
    int tid = threadIdx.x;
#pragma unroll
    for (int i = 0; i < 4; i++) {
        int d = tid + i * 256;
        float vsum = g_xs[(size_t)bn * DD + d] + tb[d];
#pragma unroll
        for (int j = 0; j < 5; j++) {
            int nn = n - 2 + j;
            if (nn >= 0 && nn < NN_SEQ)
                vsum += tw[d * 5 + j] * g_Tr[((size_t)b * NN_SEQ + nn) * DD + d];
        }
        out[(size_t)bn * DD + d] = vsum;
    }
    if (bn == 0 && tid == 0 && write_aux)
        out[(size_t)BB * NN_SEQ * DD] = g_auxval[0];
}

// ---------------- host orchestration ---------------------------------------
extern "C" void kernel_launch(void* const* d_in, const int* in_sizes, int n_in,
                              void* d_out, int out_size)
{
    const float* x    = (const float*)d_in[0];
    const float* qw   = (const float*)d_in[1];
    const float* qb   = (const float*)d_in[2];
    const float* kw   = (const float*)d_in[3];
    const float* kb   = (const float*)d_in[4];
    const float* vw   = (const float*)d_in[5];
    const float* vb   = (const float*)d_in[6];
    const float* ow   = (const float*)d_in[7];
    const float* ob   = (const float*)d_in[8];
    const float* n1g  = (const float*)d_in[9];
    const float* n1b  = (const float*)d_in[10];
    const float* n2g  = (const float*)d_in[11];
    const float* n2b  = (const float*)d_in[12];
    const float* alpha= (const float*)d_in[13];
    const float* dw7  = (const float*)d_in[14];
    const float* dw25 = (const float*)d_in[15];
    const float* dw49 = (const float*)d_in[16];
    const float* rw   = (const float*)d_in[17];
    const float* ew1  = (const float*)d_in[18];
    const float* eb1  = (const float*)d_in[19];
    const float* ew2  = (const float*)d_in[20];
    const float* eb2  = (const float*)d_in[21];
    const float* tw   = (const float*)d_in[22];
    const float* tb   = (const float*)d_in[23];
    float* out = (float*)d_out;

    float *p_Sn, *p_q, *p_k, *p_v, *p_y, *p_xs, *p_xf, *p_xfr, *p_h, *p_S, *p_lw, *p_wr;
    int *p_list, *p_cnt;
    cudaGetSymbolAddress((void**)&p_Sn, g_Sn);
    cudaGetSymbolAddress((void**)&p_q,  g_q);
    cudaGetSymbolAddress((void**)&p_k,  g_k);
    cudaGetSymbolAddress((void**)&p_v,  g_v);
    cudaGetSymbolAddress((void**)&p_y,  g_y);
    cudaGetSymbolAddress((void**)&p_xs, g_xs);
    cudaGetSymbolAddress((void**)&p_xf, g_xf);
    cudaGetSymbolAddress((void**)&p_xfr, g_xfr);
    cudaGetSymbolAddress((void**)&p_h,  g_h);
    cudaGetSymbolAddress((void**)&p_S,  g_S);
    cudaGetSymbolAddress((void**)&p_lw,  g_lw);
    cudaGetSymbolAddress((void**)&p_list, g_list);
    cudaGetSymbolAddress((void**)&p_cnt,  g_cnt);
    cudaGetSymbolAddress((void**)&p_wr,  g_wr);

    cudaFuncSetAttribute(attn_tile_kernel,
                         cudaFuncAttributeMaxDynamicSharedMemorySize, ATT_SMEM);
    cudaFuncSetAttribute(gemm_tf32,
                         cudaFuncAttributeMaxDynamicSharedMemorySize, GSMEM);

    // 0) pre-round weights to tf32 (once per launch; graph-deterministic)
    round_tf32_kernel<<<(DD * DD) / 1024, 256>>>(qw, p_wr + WR_Q, DD * DD);
    round_tf32_kernel<<<(DD * DD) / 1024, 256>>>(kw, p_wr + WR_K, DD * DD);
    round_tf32_kernel<<<(DD * DD) / 1024, 256>>>(vw, p_wr + WR_V, DD * DD);
    round_tf32_kernel<<<(DD * DD) / 1024, 256>>>(ow, p_wr + WR_O, DD * DD);
    round_tf32_kernel<<<(EE * MH * DD) / 1024, 256>>>(ew1, p_wr + WR_E1, EE * MH * DD);
    round_tf32_kernel<<<(EE * MH * DD) / 1024, 256>>>(ew2, p_wr + WR_E2, EE * MH * DD);

    // 1) decomposition + seasonal + LN1 (Sn rounded at write)
    decomp_ln1_kernel<<<BB * NN_SEQ, 256>>>(x, alpha, dw7, dw25, dw49, n1g, n1b);

    // 2) QKV projections (TF32 tensor cores, cp.async pipeline)
    dim3 gQ(DD / 128, TT / 128);
    gemm_tf32<<<gQ, 256, GSMEM>>>(p_Sn, p_wr + WR_Q, qb, nullptr, p_q, TT, DD, DD, 0, nullptr, nullptr, nullptr);
    gemm_tf32<<<gQ, 256, GSMEM>>>(p_Sn, p_wr + WR_K, kb, nullptr, p_k, TT, DD, DD, 0, nullptr, nullptr, nullptr);
    gemm_tf32<<<gQ, 256, GSMEM>>>(p_Sn, p_wr + WR_V, vb, nullptr, p_v, TT, DD, DD, 0, nullptr, nullptr, nullptr);

    // 3) ALiBi attention (flash tiles, fp32; y rounded at write)
    attn_tile_kernel<<<dim3(BB * HH, NN_SEQ / 64), 256, ATT_SMEM>>>(p_q, p_k, p_v, p_y);

    // 4) output projection fused with residual: x_s = S + (y @ ow^T + ob)
    gemm_tf32<<<gQ, 256, GSMEM>>>(p_y, p_wr + WR_O, ob, p_S, p_xs, TT, DD, DD, 0, nullptr, nullptr, nullptr);

    // 5) LN2 -> xf (exact) + xfr (rounded)
    ln_kernel<<<BB * NN_SEQ, 256>>>(p_xs, n2g, n2b, p_xf, p_xfr);

    // 6) router, token lists, aux
    router_kernel<<<TT, 128>>>(p_xf, rw);
    clear_cnt_kernel<<<1, 32>>>();
    build_lists_kernel<<<TT / 256, 256>>>();
    aux_reduce_kernel<<<1, 256>>>();

    // 7) sparse MoE: gather -> GEMM1(gelu, rounded h) -> GEMM2(scatter +=)
    dim3 gE1(MH / 128, TT / 128);
    dim3 gE2(DD / 128, TT / 128);
    for (int e = 0; e < EE; e++) {
        gemm_tf32<<<gE1, 256, GSMEM>>>(p_xfr, p_wr + WR_E1 + (size_t)e * MH * DD,
                                       eb1 + (size_t)e * MH,
                                       nullptr, p_h, TT, MH, DD, 1,
                                       p_list + e * TT, p_cnt + e, nullptr);
        gemm_tf32<<<gE2, 256, GSMEM>>>(p_h, p_wr + WR_E2 + (size_t)e * DD * MH,
                                       eb2 + (size_t)e * DD,
                                       nullptr, p_xs, TT, DD, MH, 2,
                                       p_list + e * TT, p_cnt + e, p_lw + e * TT);
    }

    // 8) trend conv + final sum + aux scalar
    int write_aux = (out_size > BB * NN_SEQ * DD) ? 1 : 0;
    final_kernel<<<BB * NN_SEQ, 256>>>(tw, tb, out, write_aux);
}

// round 9
// speedup vs baseline: 4.7874x; 1.1771x over previous
#include <cuda_runtime.h>
#include <math.h>
#include <stdint.h>

#define BB 8
#define NN_SEQ 1024
#define DD 1024
#define HH 16
#define DH 64
#define TT (BB * NN_SEQ)      // 8192 tokens
#define EE 4
#define MH 2048
#define LN_EPS 1e-5f

// ---------------- scratch (device globals; no allocations allowed) ----------
__device__ float g_Tr[BB * NN_SEQ * DD];
__device__ float g_S [BB * NN_SEQ * DD];
__device__ float g_Sn[BB * NN_SEQ * DD];    // tf32-rounded at write
__device__ float g_qkv[TT * 3 * DD];        // fused QKV, tf32-rounded at write
__device__ float g_y [BB * NN_SEQ * DD];    // tf32-rounded at write
__device__ float g_xs[BB * NN_SEQ * DD];
__device__ float g_xf[BB * NN_SEQ * DD];    // exact (router input)
__device__ float g_xfr[BB * NN_SEQ * DD];   // tf32-rounded copy (GEMM input)
__device__ float g_h [TT * MH];             // tf32-rounded at write
__device__ float g_gates[TT * EE];
__device__ float g_wts  [TT * EE];
__device__ int   g_list [EE * TT];
__device__ float g_lw   [EE * TT];
__device__ int   g_cnt  [EE];
__device__ float g_auxval[1];
__device__ float g_qkvb[3 * DD];
// pre-rounded weights: qw,kw,vw,ow (4 x 1M), ew1 (4 x 2M), ew2 (4 x 2M)
#define WR_Q  0
#define WR_K  (DD * DD)
#define WR_V  (2 * DD * DD)
#define WR_O  (3 * DD * DD)
#define WR_E1 (4 * DD * DD)
#define WR_E2 (4 * DD * DD + EE * MH * DD)
#define WR_TOTAL (4 * DD * DD + 2 * EE * MH * DD)
__device__ float g_wr[WR_TOTAL];

// ---------------- tf32 rounding helpers -------------------------------------
__device__ __forceinline__ uint32_t f2tf(float f) {
    uint32_t u;
    asm("cvt.rna.tf32.f32 %0, %1;" : "=r"(u) : "f"(f));
    return u;
}
__device__ __forceinline__ float tf32r(float f) {
    return __uint_as_float(f2tf(f));
}

__global__ __launch_bounds__(256) void round_tf32_kernel(
    const float* __restrict__ src, float* __restrict__ dst, int n)
{
    int i = (blockIdx.x * 256 + threadIdx.x) * 4;
    if (i < n) {
        float4 v = *(const float4*)&src[i];
        v.x = tf32r(v.x); v.y = tf32r(v.y);
        v.z = tf32r(v.z); v.w = tf32r(v.w);
        *(float4*)&dst[i] = v;
    }
}

__global__ __launch_bounds__(256) void concat_bias_kernel(
    const float* __restrict__ qb, const float* __restrict__ kb,
    const float* __restrict__ vb)
{
    int i = blockIdx.x * 256 + threadIdx.x;
    if (i < DD) {
        g_qkvb[i] = qb[i];
        g_qkvb[DD + i] = kb[i];
        g_qkvb[2 * DD + i] = vb[i];
    }
}

// ---------------- kernel 1: decomposition + seasonal + LN1 ------------------
__global__ __launch_bounds__(256) void decomp_ln1_kernel(
    const float* __restrict__ x, const float* __restrict__ alpha,
    const float* __restrict__ dw7, const float* __restrict__ dw25,
    const float* __restrict__ dw49,
    const float* __restrict__ n1g, const float* __restrict__ n1b)
{
    int bn = blockIdx.x;
    int b = bn / NN_SEQ, n = bn % NN_SEQ;
    int tid = threadIdx.x;

    float a0 = alpha[0], a1 = alpha[1], a2 = alpha[2];
    float mx = fmaxf(a0, fmaxf(a1, a2));
    float e0 = __expf(a0 - mx), e1 = __expf(a1 - mx), e2 = __expf(a2 - mx);
    float inv = 1.0f / (e0 + e1 + e2);
    float w0 = e0 * inv, w1 = e1 * inv, w2 = e2 * inv;

    const float* xb = x + (size_t)b * NN_SEQ * DD;
    float s_local[4];
    float sum = 0.f, sumsq = 0.f;

#pragma unroll
    for (int i = 0; i < 4; i++) {
        int d = tid + i * 256;
        float win[49];
#pragma unroll
        for (int j = 0; j < 49; j++) {
            int idx = n + j - 24;
            idx = idx < 0 ? -idx : idx;
            idx = idx >= NN_SEQ ? (2 * NN_SEQ - 2 - idx) : idx;
            win[j] = xb[(size_t)idx * DD + d];
        }
        float t7 = 0.f, t25 = 0.f, t49 = 0.f;
#pragma unroll
        for (int j = 0; j < 7; j++)  t7  += dw7 [d * 7  + j] * win[21 + j];
#pragma unroll
        for (int j = 0; j < 25; j++) t25 += dw25[d * 25 + j] * win[12 + j];
#pragma unroll
        for (int j = 0; j < 49; j++) t49 += dw49[d * 49 + j] * win[j];
        float tr = w0 * t7 + w1 * t25 + w2 * t49;
        float sv = win[24] - tr;
        g_Tr[(size_t)bn * DD + d] = tr;
        g_S [(size_t)bn * DD + d] = sv;
        s_local[i] = sv;
        sum += sv; sumsq += sv * sv;
    }

    __shared__ float sh1[256], sh2[256];
    sh1[tid] = sum; sh2[tid] = sumsq;
    __syncthreads();
    for (int o = 128; o > 0; o >>= 1) {
        if (tid < o) { sh1[tid] += sh1[tid + o]; sh2[tid] += sh2[tid + o]; }
        __syncthreads();
    }
    float mean = sh1[0] * (1.0f / DD);
    float var  = sh2[0] * (1.0f / DD) - mean * mean;
    float rstd = rsqrtf(var + LN_EPS);

#pragma unroll
    for (int i = 0; i < 4; i++) {
        int d = tid + i * 256;
        g_Sn[(size_t)bn * DD + d] =
            tf32r((s_local[i] - mean) * rstd * n1g[d] + n1b[d]);
    }
}

// ---------------- generic LN kernel (optional rounded second output) --------
__global__ __launch_bounds__(256) void ln_kernel(
    const float* __restrict__ in, const float* __restrict__ g,
    const float* __restrict__ bta, float* __restrict__ out,
    float* __restrict__ out_r)
{
    int bn = blockIdx.x;
    int tid = threadIdx.x;
    const float* row = in + (size_t)bn * DD;
    float v[4]; float sum = 0.f, sumsq = 0.f;
#pragma unroll
    for (int i = 0; i < 4; i++) {
        v[i] = row[tid + i * 256];
        sum += v[i]; sumsq += v[i] * v[i];
    }
    __shared__ float sh1[256], sh2[256];
    sh1[tid] = sum; sh2[tid] = sumsq;
    __syncthreads();
    for (int o = 128; o > 0; o >>= 1) {
        if (tid < o) { sh1[tid] += sh1[tid + o]; sh2[tid] += sh2[tid + o]; }
        __syncthreads();
    }
    float mean = sh1[0] * (1.0f / DD);
    float var  = sh2[0] * (1.0f / DD) - mean * mean;
    float rstd = rsqrtf(var + LN_EPS);
#pragma unroll
    for (int i = 0; i < 4; i++) {
        int d = tid + i * 256;
        float ov = (v[i] - mean) * rstd * g[d] + bta[d];
        out[(size_t)bn * DD + d] = ov;
        if (out_r) out_r[(size_t)bn * DD + d] = tf32r(ov);
    }
}

// ---------------- TF32 tensor-core NT GEMM, cp.async 2-stage pipeline -------
// All operands MUST be pre-rounded to tf32.
// mode 0: C = acc + bias (+ addend)            (dense, exact f32 out)
// mode 3: C = tf32r(acc + bias)                (dense, rounded out)
// mode 1: C[row] = tf32r(gelu(acc+bias)), A rows gathered via rowidx, row<cnt
// mode 2: C[rowidx[row]] += (acc + bias) * rowsw[row], row<cnt (scatter)
__device__ __forceinline__ void mma_tf32(float* d, const uint32_t* a, const uint32_t* b) {
    asm volatile(
        "mma.sync.aligned.m16n8k8.row.col.f32.tf32.tf32.f32 "
        "{%0,%1,%2,%3}, {%4,%5,%6,%7}, {%8,%9}, {%0,%1,%2,%3};"
        : "+f"(d[0]), "+f"(d[1]), "+f"(d[2]), "+f"(d[3])
        : "r"(a[0]), "r"(a[1]), "r"(a[2]), "r"(a[3]),
          "r"(b[0]), "r"(b[1]));
}

__device__ __forceinline__ void cpa16(float* dst, const float* src) {
    uint32_t d = (uint32_t)__cvta_generic_to_shared(dst);
    asm volatile("cp.async.cg.shared.global [%0], [%1], 16;\n" :: "r"(d), "l"(src));
}

#define GSMEM (2 * 4096 * 2 * (int)sizeof(float))
__global__ __launch_bounds__(256, 2) void gemm_tf32(
    const float* __restrict__ A, const float* __restrict__ W,
    const float* __restrict__ bias, const float* __restrict__ addend,
    float* __restrict__ C, int M, int Nn, int K, int mode,
    const int* __restrict__ rowidx, const int* __restrict__ cnt_ptr,
    const float* __restrict__ rowsw)
{
    int m0 = blockIdx.y * 128, n0 = blockIdx.x * 128;
    int cval = cnt_ptr ? *cnt_ptr : M;
    if (m0 >= cval) return;

    extern __shared__ float sm[];
    float* Abuf = sm;
    float* Wbuf = sm + 2 * 4096;

    int tid = threadIdx.x;
    int lrow = tid >> 1;
    int cbase = (tid & 1) * 4;

    int arow = m0 + lrow;
    if (mode == 1 && rowidx) arow = rowidx[arow < cval ? arow : (cval - 1)];
    const float* Aptr = A + (size_t)arow * K + cbase * 4;
    const float* Wptr = W + (size_t)(n0 + lrow) * K + cbase * 4;

    int dsts[4];
#pragma unroll
    for (int j = 0; j < 4; j++)
        dsts[j] = lrow * 32 + ((cbase + j) ^ (lrow & 7)) * 4;

    int lane = tid & 31, wid = tid >> 5;
    int wm = wid >> 2, wn = wid & 3;
    int g = lane >> 2, c = lane & 3;

    float acc[4][4][4];
#pragma unroll
    for (int i = 0; i < 4; i++)
#pragma unroll
        for (int j = 0; j < 4; j++)
#pragma unroll
            for (int r = 0; r < 4; r++) acc[i][j][r] = 0.f;

    int nk = K / 32;
#pragma unroll
    for (int j = 0; j < 4; j++) {
        cpa16(Abuf + dsts[j], Aptr + j * 4);
        cpa16(Wbuf + dsts[j], Wptr + j * 4);
    }
    asm volatile("cp.async.commit_group;\n" ::);

    for (int it = 0; it < nk; it++) {
        bool pre = (it + 1) < nk;
        if (pre) {
            int st = (it + 1) & 1;
            int k0 = (it + 1) * 32;
#pragma unroll
            for (int j = 0; j < 4; j++) {
                cpa16(Abuf + st * 4096 + dsts[j], Aptr + k0 + j * 4);
                cpa16(Wbuf + st * 4096 + dsts[j], Wptr + k0 + j * 4);
            }
            asm volatile("cp.async.commit_group;\n" ::);
            asm volatile("cp.async.wait_group 1;\n" ::);
        } else {
            asm volatile("cp.async.wait_group 0;\n" ::);
        }
        __syncthreads();

        const float* Ab = Abuf + (it & 1) * 4096;
        const float* Wb = Wbuf + (it & 1) * 4096;
#pragma unroll
        for (int s = 0; s < 4; s++) {
            int sw0 = ((2 * s) ^ g) * 4 + c;
            int sw1 = ((2 * s + 1) ^ g) * 4 + c;
            uint32_t af[4][4], bf[4][2];
#pragma unroll
            for (int mf = 0; mf < 4; mf++) {
                const float* pa = Ab + (wm * 64 + mf * 16 + g) * 32;
                af[mf][0] = __float_as_uint(pa[sw0]);
                af[mf][1] = __float_as_uint(pa[8 * 32 + sw0]);
                af[mf][2] = __float_as_uint(pa[sw1]);
                af[mf][3] = __float_as_uint(pa[8 * 32 + sw1]);
            }
#pragma unroll
            for (int nf = 0; nf < 4; nf++) {
                const float* pw = Wb + (wn * 32 + nf * 8 + g) * 32;
                bf[nf][0] = __float_as_uint(pw[sw0]);
                bf[nf][1] = __float_as_uint(pw[sw1]);
            }
#pragma unroll
            for (int mf = 0; mf < 4; mf++)
#pragma unroll
                for (int nf = 0; nf < 4; nf++)
                    mma_tf32(acc[mf][nf], af[mf], bf[nf]);
        }
        __syncthreads();
    }

#pragma unroll
    for (int mf = 0; mf < 4; mf++) {
#pragma unroll
        for (int half = 0; half < 2; half++) {
            int r = m0 + wm * 64 + mf * 16 + g + half * 8;
#pragma unroll
            for (int nf = 0; nf < 4; nf++) {
                int col = n0 + wn * 32 + nf * 8 + 2 * c;
                float v0 = acc[mf][nf][half * 2 + 0];
                float v1 = acc[mf][nf][half * 2 + 1];
                if (bias) { v0 += bias[col]; v1 += bias[col + 1]; }
                if (mode == 0 || mode == 3) {
                    size_t off = (size_t)r * Nn + col;
                    if (addend) {
                        float2 ad = *(const float2*)&addend[off];
                        v0 += ad.x; v1 += ad.y;
                    }
                    float2 ov = (mode == 3)
                        ? make_float2(tf32r(v0), tf32r(v1))
                        : make_float2(v0, v1);
                    *(float2*)&C[off] = ov;
                } else if (mode == 1) {
                    if (r < cval) {
                        float g0 = 0.5f * v0 * (1.0f + erff(v0 * 0.70710678118f));
                        float g1 = 0.5f * v1 * (1.0f + erff(v1 * 0.70710678118f));
                        float2 ov = make_float2(tf32r(g0), tf32r(g1));
                        *(float2*)&C[(size_t)r * Nn + col] = ov;
                    }
                } else {
                    if (r < cval) {
                        int tok = rowidx[r];
                        float w = rowsw[r];
                        size_t off = (size_t)tok * Nn + col;
                        float2 old = *(const float2*)&C[off];
                        float2 ov = make_float2(old.x + v0 * w, old.y + v1 * w);
                        *(float2*)&C[off] = ov;
                    }
                }
            }
        }
    }
}

// ---------------- attention: TF32 mma flash, 128q x (b,h) per block ---------
// smem: Ks[64key][64d] + Vt[64d][64kk] + Ps[128q][64] (also Q/V staging),
// all XOR-chunk swizzled: float (r,k) at r*64 + ((k>>2)^(r&7))*4 + (k&3).
#define ATT_SMEM ((4096 + 4096 + 8192) * (int)sizeof(float))
__global__ __launch_bounds__(256) void attn_mma_kernel(
    const float* __restrict__ qkv, float* __restrict__ y)
{
    extern __shared__ float sm[];
    float* Ks = sm;
    float* Vt = sm + 4096;
    float* Ps = sm + 8192;

    int bh = blockIdx.x;
    int b = bh >> 4, h = bh & 15;
    int q0 = blockIdx.y * 128;
    int tid = threadIdx.x, lane = tid & 31, wid = tid >> 5;
    int g = lane >> 2, c = lane & 3;
    int qb = wid * 16;
    float slope = exp2f(-0.5f * (float)(h + 1));

    const float* qkvb = qkv + (size_t)(b * NN_SEQ) * (3 * DD);

    // stage Q tile (128x64) into Ps, swizzled
    for (int i = tid; i < 128 * 16; i += 256) {
        int r = i >> 4, ch = i & 15;
        float4 v = *(const float4*)&qkvb[(size_t)(q0 + r) * (3 * DD) + h * DH + ch * 4];
        *(float4*)&Ps[r * 64 + ((ch ^ (r & 7)) << 2)] = v;
    }
    __syncthreads();

    // Q fragments to registers, scaled by 1/8 (exact power of 2; tf32-clean)
    uint32_t qf[8][4];
#pragma unroll
    for (int s = 0; s < 8; s++) {
        const float* p0 = &Ps[(qb + g) * 64];
        const float* p1 = &Ps[(qb + 8 + g) * 64];
        int sw0 = (((2 * s) ^ g) << 2) + c;
        int sw1 = (((2 * s + 1) ^ g) << 2) + c;
        qf[s][0] = __float_as_uint(p0[sw0] * 0.125f);
        qf[s][1] = __float_as_uint(p1[sw0] * 0.125f);
        qf[s][2] = __float_as_uint(p0[sw1] * 0.125f);
        qf[s][3] = __float_as_uint(p1[sw1] * 0.125f);
    }

    float oa[8][4];
#pragma unroll
    for (int i = 0; i < 8; i++)
#pragma unroll
        for (int j = 0; j < 4; j++) oa[i][j] = 0.f;
    float m_lo = -1e30f, m_hi = -1e30f, l_lo = 0.f, l_hi = 0.f;
    int qlo = q0 + qb + g, qhi = qlo + 8;

    for (int kt = 0; kt < NN_SEQ; kt += 64) {
        __syncthreads();   // protect Ps/Ks/Vt reuse across iterations
        // load K -> Ks, V -> Ps staging (row-major, swizzled)
        for (int i = tid; i < 64 * 16; i += 256) {
            int r = i >> 4, ch = i & 15;
            size_t rowoff = (size_t)(kt + r) * (3 * DD) + h * DH + ch * 4;
            int dst = r * 64 + ((ch ^ (r & 7)) << 2);
            *(float4*)&Ks[dst] = *(const float4*)&qkvb[DD + rowoff];
            *(float4*)&Ps[dst] = *(const float4*)&qkvb[2 * DD + rowoff];
        }
        __syncthreads();

        // transpose V: Ps[kk][d] -> Vt[d][kk]
        {
            int d = tid & 63, kg = tid >> 6;
#pragma unroll
            for (int i = 0; i < 16; i++) {
                int kk = kg * 16 + i;
                float v = Ps[kk * 64 + (((d >> 2) ^ (kk & 7)) << 2) + (d & 3)];
                Vt[d * 64 + (((kk >> 2) ^ (d & 7)) << 2) + (kk & 3)] = v;
            }
        }

        // S = Q @ K^T
        float sa[8][4];
#pragma unroll
        for (int i = 0; i < 8; i++)
#pragma unroll
            for (int j = 0; j < 4; j++) sa[i][j] = 0.f;
#pragma unroll
        for (int s = 0; s < 8; s++) {
            int sw0 = (((2 * s) ^ g) << 2) + c;
            int sw1 = (((2 * s + 1) ^ g) << 2) + c;
#pragma unroll
            for (int nt = 0; nt < 8; nt++) {
                const float* pk = &Ks[(nt * 8 + g) * 64];
                uint32_t bf[2];
                bf[0] = __float_as_uint(pk[sw0]);
                bf[1] = __float_as_uint(pk[sw1]);
                mma_tf32(sa[nt], qf[s], bf);
            }
        }
        __syncthreads();   // Vt writes visible; staging reads complete

        // ALiBi + online softmax (rows qlo, qhi owned by lanes 4g..4g+3)
        float mx_lo = -1e30f, mx_hi = -1e30f;
#pragma unroll
        for (int nt = 0; nt < 8; nt++) {
            int k0 = kt + nt * 8 + 2 * c;
            float d0 = (k0 > qlo) ? (float)(k0 - qlo) : 0.f;
            float d1 = (k0 + 1 > qlo) ? (float)(k0 + 1 - qlo) : 0.f;
            float d2 = (k0 > qhi) ? (float)(k0 - qhi) : 0.f;
            float d3 = (k0 + 1 > qhi) ? (float)(k0 + 1 - qhi) : 0.f;
            sa[nt][0] -= slope * d0; sa[nt][1] -= slope * d1;
            sa[nt][2] -= slope * d2; sa[nt][3] -= slope * d3;
            mx_lo = fmaxf(mx_lo, fmaxf(sa[nt][0], sa[nt][1]));
            mx_hi = fmaxf(mx_hi, fmaxf(sa[nt][2], sa[nt][3]));
        }
        mx_lo = fmaxf(mx_lo, __shfl_xor_sync(0xffffffffu, mx_lo, 1));
        mx_lo = fmaxf(mx_lo, __shfl_xor_sync(0xffffffffu, mx_lo, 2));
        mx_hi = fmaxf(mx_hi, __shfl_xor_sync(0xffffffffu, mx_hi, 1));
        mx_hi = fmaxf(mx_hi, __shfl_xor_sync(0xffffffffu, mx_hi, 2));
        float mn_lo = fmaxf(m_lo, mx_lo), mn_hi = fmaxf(m_hi, mx_hi);
        float cc_lo = __expf(m_lo - mn_lo), cc_hi = __expf(m_hi - mn_hi);
        m_lo = mn_lo; m_hi = mn_hi;

        float rs_lo = 0.f, rs_hi = 0.f;
#pragma unroll
        for (int nt = 0; nt < 8; nt++) {
            float p0 = __expf(sa[nt][0] - mn_lo), p1 = __expf(sa[nt][1] - mn_lo);
            float p2 = __expf(sa[nt][2] - mn_hi), p3 = __expf(sa[nt][3] - mn_hi);
            rs_lo += p0 + p1; rs_hi += p2 + p3;
            int col = nt * 8 + 2 * c;
            int ch = col >> 2, off = col & 3;
            *(float2*)&Ps[(qb + g) * 64 + ((ch ^ g) << 2) + off] =
                make_float2(tf32r(p0), tf32r(p1));
            *(float2*)&Ps[(qb + 8 + g) * 64 + ((ch ^ g) << 2) + off] =
                make_float2(tf32r(p2), tf32r(p3));
        }
        rs_lo += __shfl_xor_sync(0xffffffffu, rs_lo, 1);
        rs_lo += __shfl_xor_sync(0xffffffffu, rs_lo, 2);
        rs_hi += __shfl_xor_sync(0xffffffffu, rs_hi, 1);
        rs_hi += __shfl_xor_sync(0xffffffffu, rs_hi, 2);
        l_lo = l_lo * cc_lo + rs_lo;
        l_hi = l_hi * cc_hi + rs_hi;
#pragma unroll
        for (int nt = 0; nt < 8; nt++) {
            oa[nt][0] *= cc_lo; oa[nt][1] *= cc_lo;
            oa[nt][2] *= cc_hi; oa[nt][3] *= cc_hi;
        }
        __syncwarp();

        // O += P @ V  (Ps rows are warp-private; Vt synced above)
#pragma unroll
        for (int s2 = 0; s2 < 8; s2++) {
            int sw0 = (((2 * s2) ^ g) << 2) + c;
            int sw1 = (((2 * s2 + 1) ^ g) << 2) + c;
            const float* pl = &Ps[(qb + g) * 64];
            const float* ph = &Ps[(qb + 8 + g) * 64];
            uint32_t af[4];
            af[0] = __float_as_uint(pl[sw0]);
            af[1] = __float_as_uint(ph[sw0]);
            af[2] = __float_as_uint(pl[sw1]);
            af[3] = __float_as_uint(ph[sw1]);
#pragma unroll
            for (int nt = 0; nt < 8; nt++) {
                const float* pv = &Vt[(nt * 8 + g) * 64];
                uint32_t bf[2];
                bf[0] = __float_as_uint(pv[sw0]);
                bf[1] = __float_as_uint(pv[sw1]);
                mma_tf32(oa[nt], af, bf);
            }
        }
    }

    float il_lo = 1.0f / l_lo, il_hi = 1.0f / l_hi;
#pragma unroll
    for (int nt = 0; nt < 8; nt++) {
        int col = h * DH + nt * 8 + 2 * c;
        size_t rlo = (size_t)(b * NN_SEQ + qlo) * DD + col;
        *(float2*)&y[rlo] =
            make_float2(tf32r(oa[nt][0] * il_lo), tf32r(oa[nt][1] * il_lo));
        *(float2*)&y[rlo + 8 * DD] =
            make_float2(tf32r(oa[nt][2] * il_hi), tf32r(oa[nt][3] * il_hi));
    }
}

// ---------------- router: gates + top-2 weights -----------------------------
__global__ __launch_bounds__(128) void router_kernel(
    const float* __restrict__ xf, const float* __restrict__ rw)
{
    int t = blockIdx.x;
    int lane = threadIdx.x & 31, wrp = threadIdx.x >> 5;
    const float* xr = xf + (size_t)t * DD;
    const float* wr = rw + (size_t)wrp * DD;
    float s = 0.f;
    for (int i = lane; i < DD; i += 32) s += xr[i] * wr[i];
#pragma unroll
    for (int o = 16; o > 0; o >>= 1) s += __shfl_xor_sync(0xffffffffu, s, o);
    __shared__ float sh[4];
    if (lane == 0) sh[wrp] = s;
    __syncthreads();
    if (threadIdx.x == 0) {
        float g[4]; float mx = -1e30f;
#pragma unroll
        for (int e = 0; e < EE; e++) { g[e] = sh[e]; mx = fmaxf(mx, g[e]); }
        float sum = 0.f;
#pragma unroll
        for (int e = 0; e < EE; e++) { g[e] = __expf(g[e] - mx); sum += g[e]; }
        float inv = 1.0f / sum;
#pragma unroll
        for (int e = 0; e < EE; e++) { g[e] *= inv; g_gates[t * EE + e] = g[e]; }
        int i1 = 0;
#pragma unroll
        for (int e = 1; e < EE; e++) if (g[e] > g[i1]) i1 = e;
        int i2 = -1;
#pragma unroll
        for (int e = 0; e < EE; e++)
            if (e != i1 && (i2 < 0 || g[e] > g[i2])) i2 = e;
        float norm = fmaxf(g[i1] + g[i2], 1e-9f);
        float w4[4] = {0.f, 0.f, 0.f, 0.f};
        w4[i1] = g[i1] / norm;
        w4[i2] = g[i2] / norm;
#pragma unroll
        for (int e = 0; e < EE; e++) g_wts[t * EE + e] = w4[e];
    }
}

// ---------------- expert token lists ----------------------------------------
__global__ void clear_cnt_kernel() {
    if (threadIdx.x < EE) g_cnt[threadIdx.x] = 0;
}

__global__ __launch_bounds__(256) void build_lists_kernel() {
    int t = blockIdx.x * 256 + threadIdx.x;
    if (t >= TT) return;
#pragma unroll
    for (int e = 0; e < EE; e++) {
        float w = g_wts[t * EE + e];
        if (w > 0.f) {
            int p = atomicAdd(&g_cnt[e], 1);
            g_list[e * TT + p] = t;
            g_lw[e * TT + p] = w;
        }
    }
}

// ---------------- deterministic aux reduction -------------------------------
__global__ __launch_bounds__(256) void aux_reduce_kernel()
{
    int tid = threadIdx.x;
    float sg[EE] = {0.f, 0.f, 0.f, 0.f};
    float sc[EE] = {0.f, 0.f, 0.f, 0.f};
    for (int t = tid; t < TT; t += 256) {
#pragma unroll
        for (int e = 0; e < EE; e++) {
            sg[e] += g_gates[t * EE + e];
            sc[e] += (g_wts[t * EE + e] > 0.f) ? 1.f : 0.f;
        }
    }
    __shared__ float sh[256];
    float aux = 0.f;
#pragma unroll
    for (int e = 0; e < EE; e++) {
        sh[tid] = sg[e]; __syncthreads();
        for (int o = 128; o > 0; o >>= 1) {
            if (tid < o) sh[tid] += sh[tid + o];
            __syncthreads();
        }
        float tot_g = sh[0]; __syncthreads();
        sh[tid] = sc[e]; __syncthreads();
        for (int o = 128; o > 0; o >>= 1) {
            if (tid < o) sh[tid] += sh[tid + o];
            __syncthreads();
        }
        float tot_c = sh[0]; __syncthreads();
        aux += (tot_g / (float)TT) * (tot_c / (float)TT);
    }
    if (tid == 0) g_auxval[0] = (float)EE * aux;
}

// ---------------- final: + trend depthwise conv(k=5) + aux ------------------
__global__ __launch_bounds__(256) void final_kernel(
    const float* __restrict__ tw, const float* __restrict__ tb,
    float* __restrict__ out, int write_aux)
{
    int bn = blockIdx.x;
    int b = bn / NN_SEQ, n = bn % NN_SEQ;
    int tid = threadIdx.x;
#pragma unroll
    for (int i = 0; i < 4; i++) {
        int d = tid + i * 256;
        float vsum = g_xs[(size_t)bn * DD + d] + tb[d];
#pragma unroll
        for (int j = 0; j < 5; j++) {
            int nn = n - 2 + j;
            if (nn >= 0 && nn < NN_SEQ)
                vsum += tw[d * 5 + j] * g_Tr[((size_t)b * NN_SEQ + nn) * DD + d];
        }
        out[(size_t)bn * DD + d] = vsum;
    }
    if (bn == 0 && tid == 0 && write_aux)
        out[(size_t)BB * NN_SEQ * DD] = g_auxval[0];
}

// ---------------- host orchestration ---------------------------------------
extern "C" void kernel_launch(void* const* d_in, const int* in_sizes, int n_in,
                              void* d_out, int out_size)
{
    const float* x    = (const float*)d_in[0];
    const float* qw   = (const float*)d_in[1];
    const float* qb   = (const float*)d_in[2];
    const float* kw   = (const float*)d_in[3];
    const float* kb   = (const float*)d_in[4];
    const float* vw   = (const float*)d_in[5];
    const float* vb   = (const float*)d_in[6];
    const float* ow   = (const float*)d_in[7];
    const float* ob   = (const float*)d_in[8];
    const float* n1g  = (const float*)d_in[9];
    const float* n1b  = (const float*)d_in[10];
    const float* n2g  = (const float*)d_in[11];
    const float* n2b  = (const float*)d_in[12];
    const float* alpha= (const float*)d_in[13];
    const float* dw7  = (const float*)d_in[14];
    const float* dw25 = (const float*)d_in[15];
    const float* dw49 = (const float*)d_in[16];
    const float* rw   = (const float*)d_in[17];
    const float* ew1  = (const float*)d_in[18];
    const float* eb1  = (const float*)d_in[19];
    const float* ew2  = (const float*)d_in[20];
    const float* eb2  = (const float*)d_in[21];
    const float* tw   = (const float*)d_in[22];
    const float* tb   = (const float*)d_in[23];
    float* out = (float*)d_out;

    float *p_Sn, *p_qkv, *p_y, *p_xs, *p_xf, *p_xfr, *p_h, *p_S, *p_lw, *p_wr;
    int *p_list, *p_cnt;
    cudaGetSymbolAddress((void**)&p_Sn, g_Sn);
    cudaGetSymbolAddress((void**)&p_qkv, g_qkv);
    cudaGetSymbolAddress((void**)&p_y,  g_y);
    cudaGetSymbolAddress((void**)&p_xs, g_xs);
    cudaGetSymbolAddress((void**)&p_xf, g_xf);
    cudaGetSymbolAddress((void**)&p_xfr, g_xfr);
    cudaGetSymbolAddress((void**)&p_h,  g_h);
    cudaGetSymbolAddress((void**)&p_S,  g_S);
    cudaGetSymbolAddress((void**)&p_lw,  g_lw);
    cudaGetSymbolAddress((void**)&p_list, g_list);
    cudaGetSymbolAddress((void**)&p_cnt,  g_cnt);
    cudaGetSymbolAddress((void**)&p_wr,  g_wr);
    float* p_qkvb;
    cudaGetSymbolAddress((void**)&p_qkvb, g_qkvb);

    cudaFuncSetAttribute(attn_mma_kernel,
                         cudaFuncAttributeMaxDynamicSharedMemorySize, ATT_SMEM);
    cudaFuncSetAttribute(gemm_tf32,
                         cudaFuncAttributeMaxDynamicSharedMemorySize, GSMEM);

    // 0) pre-round weights; concat QKV biases
    round_tf32_kernel<<<(DD * DD) / 1024, 256>>>(qw, p_wr + WR_Q, DD * DD);
    round_tf32_kernel<<<(DD * DD) / 1024, 256>>>(kw, p_wr + WR_K, DD * DD);
    round_tf32_kernel<<<(DD * DD) / 1024, 256>>>(vw, p_wr + WR_V, DD * DD);
    round_tf32_kernel<<<(DD * DD) / 1024, 256>>>(ow, p_wr + WR_O, DD * DD);
    round_tf32_kernel<<<(EE * MH * DD) / 1024, 256>>>(ew1, p_wr + WR_E1, EE * MH * DD);
    round_tf32_kernel<<<(EE * MH * DD) / 1024, 256>>>(ew2, p_wr + WR_E2, EE * MH * DD);
    concat_bias_kernel<<<(DD + 255) / 256, 256>>>(qb, kb, vb);

    // 1) decomposition + seasonal + LN1 (Sn rounded)
    decomp_ln1_kernel<<<BB * NN_SEQ, 256>>>(x, alpha, dw7, dw25, dw49, n1g, n1b);

    // 2) fused QKV projection -> g_qkv [T, 3072], rounded (mode 3)
    gemm_tf32<<<dim3(3 * DD / 128, TT / 128), 256, GSMEM>>>(
        p_Sn, p_wr + WR_Q, p_qkvb, nullptr, p_qkv, TT, 3 * DD, DD, 3,
        nullptr, nullptr, nullptr);

    // 3) ALiBi attention: TF32 mma flash tiles
    attn_mma_kernel<<<dim3(BB * HH, NN_SEQ / 128), 256, ATT_SMEM>>>(p_qkv, p_y);

    // 4) output projection fused with residual: x_s = S + (y @ ow^T + ob)
    dim3 gQ(DD / 128, TT / 128);
    gemm_tf32<<<gQ, 256, GSMEM>>>(p_y, p_wr + WR_O, ob, p_S, p_xs, TT, DD, DD, 0,
                                  nullptr, nullptr, nullptr);

    // 5) LN2 -> xf (exact) + xfr (rounded)
    ln_kernel<<<BB * NN_SEQ, 256>>>(p_xs, n2g, n2b, p_xf, p_xfr);

    // 6) router, token lists, aux
    router_kernel<<<TT, 128>>>(p_xf, rw);
    clear_cnt_kernel<<<1, 32>>>();
    build_lists_kernel<<<TT / 256, 256>>>();
    aux_reduce_kernel<<<1, 256>>>();

    // 7) sparse MoE: gather -> GEMM1(gelu, rounded h) -> GEMM2(scatter +=)
    dim3 gE1(MH / 128, TT / 128);
    dim3 gE2(DD / 128, TT / 128);
    for (int e = 0; e < EE; e++) {
        gemm_tf32<<<gE1, 256, GSMEM>>>(p_xfr, p_wr + WR_E1 + (size_t)e * MH * DD,
                                       eb1 + (size_t)e * MH,
                                       nullptr, p_h, TT, MH, DD, 1,
                                       p_list + e * TT, p_cnt + e, nullptr);
        gemm_tf32<<<gE2, 256, GSMEM>>>(p_h, p_wr + WR_E2 + (size_t)e * DD * MH,
                                       eb2 + (size_t)e * DD,
                                       nullptr, p_xs, TT, DD, MH, 2,
                                       p_list + e * TT, p_cnt + e, p_lw + e * TT);
    }

    // 8) trend conv + final sum + aux scalar
    int write_aux = (out_size > BB * NN_SEQ * DD) ? 1 : 0;
    final_kernel<<<BB * NN_SEQ, 256>>>(tw, tb, out, write_aux);
}